// round 1
// baseline (speedup 1.0000x reference)
#include <cuda_runtime.h>

#define BN 4
#define SQ 1024
#define DIM 1024
#define NH 16
#define HD 64
#define NEGMASK (-10000000.0f)

// Scratch: Q, K, V in [B, H, S, HD] layout
__device__ float g_q[BN * NH * SQ * HD];
__device__ float g_k[BN * NH * SQ * HD];
__device__ float g_v[BN * NH * SQ * HD];

// ---------------------------------------------------------------------------
// QKV projection GEMM: out[b,h,s,hd] = x[m,:] @ W[:,n] + bias[n]
// m = b*SQ+s (M=4096), n = h*HD+hd (N=1024), K=1024.
// Tile 128x128x8, 256 threads, 8x8 register micro-tile.
// blockIdx.z selects which of Q/K/V.
// ---------------------------------------------------------------------------
__global__ __launch_bounds__(256, 2) void qkv_gemm(
    const float* __restrict__ x,
    const float* __restrict__ Wq, const float* __restrict__ bq,
    const float* __restrict__ Wk, const float* __restrict__ bk,
    const float* __restrict__ Wv, const float* __restrict__ bv)
{
    __shared__ float As[8][132];  // [k][m], padded to kill store conflicts
    __shared__ float Bs[8][132];  // [k][n]

    const float* W;
    const float* bias;
    float* out;
    if (blockIdx.z == 0)      { W = Wq; bias = bq; out = g_q; }
    else if (blockIdx.z == 1) { W = Wk; bias = bk; out = g_k; }
    else                      { W = Wv; bias = bv; out = g_v; }

    const int tid = threadIdx.x;
    const int tx = tid & 15;        // 0..15 -> 8 output cols each
    const int ty = tid >> 4;        // 0..15 -> 8 output rows each
    const int m0 = blockIdx.y * 128;
    const int n0 = blockIdx.x * 128;

    // A-load mapping: 128 rows x 8 cols, 2 threads per row (float4 each)
    const int lr = tid >> 1;
    const int lc = (tid & 1) * 4;
    // B-load mapping: 8 rows x 128 cols, 32 threads per row (float4 each)
    const int wr = tid >> 5;
    const int wc = (tid & 31) * 4;

    const float* xp = x + (size_t)(m0 + lr) * DIM + lc;
    const float* wp = W + (size_t)wr * DIM + n0 + wc;

    float acc[8][8];
    #pragma unroll
    for (int i = 0; i < 8; i++)
        #pragma unroll
        for (int j = 0; j < 8; j++) acc[i][j] = 0.0f;

    for (int k0 = 0; k0 < DIM; k0 += 8) {
        float4 av = *(const float4*)(xp + k0);
        float4 bv4 = *(const float4*)(wp + (size_t)k0 * DIM);
        __syncthreads();
        As[lc + 0][lr] = av.x;
        As[lc + 1][lr] = av.y;
        As[lc + 2][lr] = av.z;
        As[lc + 3][lr] = av.w;
        *(float4*)&Bs[wr][wc] = bv4;
        __syncthreads();

        #pragma unroll
        for (int k = 0; k < 8; k++) {
            float a[8], b[8];
            float4 a0 = *(const float4*)&As[k][ty * 8];
            float4 a1 = *(const float4*)&As[k][ty * 8 + 4];
            float4 b0 = *(const float4*)&Bs[k][tx * 8];
            float4 b1 = *(const float4*)&Bs[k][tx * 8 + 4];
            a[0]=a0.x; a[1]=a0.y; a[2]=a0.z; a[3]=a0.w;
            a[4]=a1.x; a[5]=a1.y; a[6]=a1.z; a[7]=a1.w;
            b[0]=b0.x; b[1]=b0.y; b[2]=b0.z; b[3]=b0.w;
            b[4]=b1.x; b[5]=b1.y; b[6]=b1.z; b[7]=b1.w;
            #pragma unroll
            for (int i = 0; i < 8; i++)
                #pragma unroll
                for (int j = 0; j < 8; j++)
                    acc[i][j] = fmaf(a[i], b[j], acc[i][j]);
        }
    }

    // Epilogue: add bias, scatter to [B,H,S,HD]
    #pragma unroll
    for (int i = 0; i < 8; i++) {
        int m = m0 + ty * 8 + i;
        int bb = m >> 10;
        int s  = m & 1023;
        #pragma unroll
        for (int j = 0; j < 8; j += 4) {
            int n = n0 + tx * 8 + j;
            int hh = n >> 6;
            int hd = n & 63;
            float4 r;
            r.x = acc[i][j + 0] + bias[n + 0];
            r.y = acc[i][j + 1] + bias[n + 1];
            r.z = acc[i][j + 2] + bias[n + 2];
            r.w = acc[i][j + 3] + bias[n + 3];
            *(float4*)&out[(((size_t)bb * NH + hh) * SQ + s) * HD + hd] = r;
        }
    }
}

// ---------------------------------------------------------------------------
// Flash-style attention: one thread owns one query row (full online-softmax
// state in registers, no cross-thread reductions). K/V tiles in SMEM
// (broadcast reads), adj read direct (L2-resident, 16x head reuse).
// Grid: (S/128, B*H), 128 threads.
// ---------------------------------------------------------------------------
__global__ __launch_bounds__(128) void attn_kernel(
    const float* __restrict__ adj, float* __restrict__ hout)
{
    const int KT = 16;
    __shared__ float Ks[KT][HD];
    __shared__ float Vs[KT][HD];

    const int bh = blockIdx.y;           // b*NH + h
    const int b = bh >> 4;
    const int h = bh & 15;
    const int row = blockIdx.x * 128 + threadIdx.x;

    const float* qp = g_q + ((size_t)bh * SQ + row) * HD;
    const float* kb = g_k + (size_t)bh * SQ * HD;
    const float* vb = g_v + (size_t)bh * SQ * HD;
    const float* ar = adj + ((size_t)b * SQ + row) * SQ;

    float q[HD];
    #pragma unroll
    for (int d = 0; d < HD; d += 4) {
        float4 t = *(const float4*)(qp + d);
        q[d] = t.x; q[d + 1] = t.y; q[d + 2] = t.z; q[d + 3] = t.w;
    }
    float o[HD];
    #pragma unroll
    for (int d = 0; d < HD; d++) o[d] = 0.0f;
    float mmax = -3.4e38f;
    float l = 0.0f;

    for (int kv0 = 0; kv0 < SQ; kv0 += KT) {
        __syncthreads();
        // cooperative K/V tile load: KT*HD/4 = 256 float4 each, 128 threads
        #pragma unroll
        for (int i = threadIdx.x; i < KT * HD / 4; i += 128) {
            ((float4*)Ks)[i] = ((const float4*)(kb + (size_t)kv0 * HD))[i];
            ((float4*)Vs)[i] = ((const float4*)(vb + (size_t)kv0 * HD))[i];
        }
        __syncthreads();

        float s[KT];
        #pragma unroll
        for (int k = 0; k < KT; k++) {
            float acc = 0.0f;
            #pragma unroll
            for (int d = 0; d < HD; d += 4) {
                float4 kv = *(const float4*)&Ks[k][d];
                acc = fmaf(q[d],     kv.x, acc);
                acc = fmaf(q[d + 1], kv.y, acc);
                acc = fmaf(q[d + 2], kv.z, acc);
                acc = fmaf(q[d + 3], kv.w, acc);
            }
            s[k] = acc * 0.125f;   // 1/sqrt(64)
        }
        // adjacency mask
        #pragma unroll
        for (int k4 = 0; k4 < KT; k4 += 4) {
            float4 aj = *(const float4*)(ar + kv0 + k4);
            if (aj.x < 0.5f) s[k4 + 0] += NEGMASK;
            if (aj.y < 0.5f) s[k4 + 1] += NEGMASK;
            if (aj.z < 0.5f) s[k4 + 2] += NEGMASK;
            if (aj.w < 0.5f) s[k4 + 3] += NEGMASK;
        }
        // online softmax
        float tmax = mmax;
        #pragma unroll
        for (int k = 0; k < KT; k++) tmax = fmaxf(tmax, s[k]);
        float corr = __expf(mmax - tmax);
        l *= corr;
        #pragma unroll
        for (int d = 0; d < HD; d++) o[d] *= corr;
        mmax = tmax;
        #pragma unroll
        for (int k = 0; k < KT; k++) {
            float p = __expf(s[k] - tmax);
            l += p;
            #pragma unroll
            for (int d = 0; d < HD; d += 4) {
                float4 vv = *(const float4*)&Vs[k][d];
                o[d]     = fmaf(p, vv.x, o[d]);
                o[d + 1] = fmaf(p, vv.y, o[d + 1]);
                o[d + 2] = fmaf(p, vv.z, o[d + 2]);
                o[d + 3] = fmaf(p, vv.w, o[d + 3]);
            }
        }
    }

    const float inv = 1.0f / l;
    float* op = hout + ((size_t)b * SQ + row) * DIM + h * HD;
    #pragma unroll
    for (int d = 0; d < HD; d += 4) {
        float4 r;
        r.x = fmaxf(o[d]     * inv, 0.0f);
        r.y = fmaxf(o[d + 1] * inv, 0.0f);
        r.z = fmaxf(o[d + 2] * inv, 0.0f);
        r.w = fmaxf(o[d + 3] * inv, 0.0f);
        *(float4*)(op + d) = r;
    }
}

// ---------------------------------------------------------------------------
extern "C" void kernel_launch(void* const* d_in, const int* in_sizes, int n_in,
                              void* d_out, int out_size)
{
    const float* x   = (const float*)d_in[0];
    const float* adj = (const float*)d_in[1];
    const float* Wq  = (const float*)d_in[2];
    const float* bq  = (const float*)d_in[3];
    const float* Wk  = (const float*)d_in[4];
    const float* bk  = (const float*)d_in[5];
    const float* Wv  = (const float*)d_in[6];
    const float* bv  = (const float*)d_in[7];

    float* hout   = (float*)d_out;
    float* adjout = (float*)d_out + (size_t)BN * SQ * DIM;

    // 1) QKV projections into headed layout
    dim3 ggrid(DIM / 128, (BN * SQ) / 128, 3);
    qkv_gemm<<<ggrid, 256>>>(x, Wq, bq, Wk, bk, Wv, bv);

    // 2) masked flash attention + relu -> first half of output
    dim3 agrid(SQ / 128, BN * NH);
    attn_kernel<<<agrid, 128>>>(adj, hout);

    // 3) pass-through adj -> second half of output
    cudaMemcpyAsync(adjout, adj, (size_t)BN * SQ * SQ * sizeof(float),
                    cudaMemcpyDeviceToDevice);
}

// round 4
// speedup vs baseline: 3.8155x; 3.8155x over previous
#include <cuda_runtime.h>
#include <cuda_bf16.h>
#include <cstdint>

#define BN 4
#define SQ 1024
#define DIM 1024
#define NH 16
#define HD 64
#define BH (BN*NH)
#define NEGMASK (-10000000.0f)

// ---------------- scratch (device globals; no allocs allowed) ----------------
__device__ __nv_bfloat16 g_x_hi[BN*SQ*DIM];
__device__ __nv_bfloat16 g_x_lo[BN*SQ*DIM];
__device__ __nv_bfloat16 g_wt_hi[3*DIM*DIM];   // W^T  [n][k]
__device__ __nv_bfloat16 g_wt_lo[3*DIM*DIM];
__device__ __nv_bfloat16 g_q_hi[BH*SQ*HD];
__device__ __nv_bfloat16 g_q_lo[BH*SQ*HD];
__device__ __nv_bfloat16 g_k_hi[BH*SQ*HD];
__device__ __nv_bfloat16 g_k_lo[BH*SQ*HD];
__device__ __nv_bfloat16 g_vt_hi[BH*HD*SQ];    // V^T  [bh][hd][s]
__device__ __nv_bfloat16 g_vt_lo[BH*HD*SQ];

// ---------------- helpers ----------------
__device__ __forceinline__ void split2(float a, float b, uint32_t& hi, uint32_t& lo) {
    __nv_bfloat162 h = __floats2bfloat162_rn(a, b);        // x=a, y=b
    float ra = a - __bfloat162float(h.x);
    float rb = b - __bfloat162float(h.y);
    __nv_bfloat162 l = __floats2bfloat162_rn(ra, rb);
    hi = *reinterpret_cast<uint32_t*>(&h);
    lo = *reinterpret_cast<uint32_t*>(&l);
}

__device__ __forceinline__ void mma_bf16(float* c, const uint32_t* a, uint32_t b0, uint32_t b1) {
    asm volatile(
        "mma.sync.aligned.m16n8k16.row.col.f32.bf16.bf16.f32 "
        "{%0,%1,%2,%3}, {%4,%5,%6,%7}, {%8,%9}, {%0,%1,%2,%3};\n"
        : "+f"(c[0]), "+f"(c[1]), "+f"(c[2]), "+f"(c[3])
        : "r"(a[0]), "r"(a[1]), "r"(a[2]), "r"(a[3]), "r"(b0), "r"(b1));
}

// ---------------- 1) split x into bf16 hi/lo ----------------
__global__ void split_x_kernel(const float* __restrict__ x) {
    size_t i = ((size_t)blockIdx.x * 256 + threadIdx.x) * 4;
    float4 v = *(const float4*)(x + i);
    uint32_t h0, l0, h1, l1;
    split2(v.x, v.y, h0, l0);
    split2(v.z, v.w, h1, l1);
    uint2 hh; hh.x = h0; hh.y = h1;
    uint2 ll; ll.x = l0; ll.y = l1;
    *(uint2*)(g_x_hi + i) = hh;
    *(uint2*)(g_x_lo + i) = ll;
}

// ---------------- 2) transpose + split W -> Wt[n][k] hi/lo ----------------
__global__ void split_w_kernel(const float* __restrict__ Wq,
                               const float* __restrict__ Wk,
                               const float* __restrict__ Wv) {
    __shared__ float t[32][33];
    int z = blockIdx.z;
    const float* W = (z == 0) ? Wq : (z == 1) ? Wk : Wv;
    __nv_bfloat16* wth = g_wt_hi + (size_t)z * DIM * DIM;
    __nv_bfloat16* wtl = g_wt_lo + (size_t)z * DIM * DIM;
    int n0 = blockIdx.x * 32, k0 = blockIdx.y * 32;
    int tx = threadIdx.x, ty = threadIdx.y;
    #pragma unroll
    for (int r = 0; r < 4; r++)
        t[ty + 8 * r][tx] = W[(size_t)(k0 + ty + 8 * r) * DIM + n0 + tx];
    __syncthreads();
    #pragma unroll
    for (int r = 0; r < 4; r++) {
        float v = t[tx][ty + 8 * r];                      // W[k0+tx][n0+ty+8r]
        size_t idx = (size_t)(n0 + ty + 8 * r) * DIM + k0 + tx;
        __nv_bfloat16 hb = __float2bfloat16(v);
        wth[idx] = hb;
        wtl[idx] = __float2bfloat16(v - __bfloat162float(hb));
    }
}

// ---------------- 3) QKV GEMM: bf16x3 tensor, 128x128 CTA tile ----------------
// warp grid 2x4, warp tile 64(m) x 32(n); k staged 32 per iter.
__global__ __launch_bounds__(256) void qkv_gemm(const float* __restrict__ bq,
                                                const float* __restrict__ bk,
                                                const float* __restrict__ bv) {
    __shared__ __nv_bfloat16 Xh[128][40], Xl[128][40], Wh[128][40], Wl[128][40];
    const int z = blockIdx.z;
    const __nv_bfloat16* wth = g_wt_hi + (size_t)z * DIM * DIM;
    const __nv_bfloat16* wtl = g_wt_lo + (size_t)z * DIM * DIM;
    const float* bias = (z == 0) ? bq : (z == 1) ? bk : bv;
    const int m0 = blockIdx.y * 128, n0 = blockIdx.x * 128;
    const int tid = threadIdx.x;
    const int warp = tid >> 5, lane = tid & 31, g = lane >> 2, tg = lane & 3;
    const int wy = warp >> 2, wx = warp & 3;   // wy 0..1, wx 0..3

    float acc[4][4][4];
    #pragma unroll
    for (int a = 0; a < 4; a++)
        #pragma unroll
        for (int b = 0; b < 4; b++)
            #pragma unroll
            for (int c = 0; c < 4; c++) acc[a][b][c] = 0.0f;

    for (int k0 = 0; k0 < DIM; k0 += 32) {
        __syncthreads();
        #pragma unroll
        for (int c = tid; c < 512; c += 256) {
            int r = c >> 2, cc = (c & 3) * 8;
            *(uint4*)&Xh[r][cc] = *(const uint4*)(g_x_hi + (size_t)(m0 + r) * DIM + k0 + cc);
            *(uint4*)&Xl[r][cc] = *(const uint4*)(g_x_lo + (size_t)(m0 + r) * DIM + k0 + cc);
            *(uint4*)&Wh[r][cc] = *(const uint4*)(wth + (size_t)(n0 + r) * DIM + k0 + cc);
            *(uint4*)&Wl[r][cc] = *(const uint4*)(wtl + (size_t)(n0 + r) * DIM + k0 + cc);
        }
        __syncthreads();
        #pragma unroll
        for (int kt = 0; kt < 2; kt++) {
            uint32_t ah[4][4], al[4][4];
            const int cI = kt * 16 + 2 * tg;
            #pragma unroll
            for (int mt = 0; mt < 4; mt++) {
                int r = wy * 64 + mt * 16;
                ah[mt][0] = *(uint32_t*)&Xh[r + g][cI];
                ah[mt][1] = *(uint32_t*)&Xh[r + g + 8][cI];
                ah[mt][2] = *(uint32_t*)&Xh[r + g][cI + 8];
                ah[mt][3] = *(uint32_t*)&Xh[r + g + 8][cI + 8];
                al[mt][0] = *(uint32_t*)&Xl[r + g][cI];
                al[mt][1] = *(uint32_t*)&Xl[r + g + 8][cI];
                al[mt][2] = *(uint32_t*)&Xl[r + g][cI + 8];
                al[mt][3] = *(uint32_t*)&Xl[r + g + 8][cI + 8];
            }
            #pragma unroll
            for (int nt = 0; nt < 4; nt++) {
                int rn = wx * 32 + nt * 8 + g;
                uint32_t bh0 = *(uint32_t*)&Wh[rn][cI];
                uint32_t bh1 = *(uint32_t*)&Wh[rn][cI + 8];
                uint32_t bl0 = *(uint32_t*)&Wl[rn][cI];
                uint32_t bl1 = *(uint32_t*)&Wl[rn][cI + 8];
                #pragma unroll
                for (int mt = 0; mt < 4; mt++) {
                    mma_bf16(acc[mt][nt], ah[mt], bh0, bh1);
                    mma_bf16(acc[mt][nt], ah[mt], bl0, bl1);
                    mma_bf16(acc[mt][nt], al[mt], bh0, bh1);
                }
            }
        }
    }

    // epilogue: +bias, split to bf16 hi/lo, scatter to headed layouts
    #pragma unroll
    for (int mt = 0; mt < 4; mt++) {
        #pragma unroll
        for (int nt = 0; nt < 4; nt++) {
            int n = n0 + wx * 32 + nt * 8 + 2 * tg;
            float b0 = bias[n], b1 = bias[n + 1];
            int hh = n >> 6, hd = n & 63;
            #pragma unroll
            for (int half = 0; half < 2; half++) {
                int m = m0 + wy * 64 + mt * 16 + g + half * 8;
                float v0 = acc[mt][nt][half * 2 + 0] + b0;
                float v1 = acc[mt][nt][half * 2 + 1] + b1;
                int bb = m >> 10, s = m & 1023;
                uint32_t hi, lo;
                split2(v0, v1, hi, lo);
                if (z == 0) {
                    size_t base = ((size_t)(bb * NH + hh) * SQ + s) * HD + hd;
                    *(uint32_t*)(g_q_hi + base) = hi;
                    *(uint32_t*)(g_q_lo + base) = lo;
                } else if (z == 1) {
                    size_t base = ((size_t)(bb * NH + hh) * SQ + s) * HD + hd;
                    *(uint32_t*)(g_k_hi + base) = hi;
                    *(uint32_t*)(g_k_lo + base) = lo;
                } else {
                    size_t v0i = ((size_t)(bb * NH + hh) * HD + hd) * SQ + s;
                    __nv_bfloat162 hb = *reinterpret_cast<__nv_bfloat162*>(&hi);
                    __nv_bfloat162 lb = *reinterpret_cast<__nv_bfloat162*>(&lo);
                    g_vt_hi[v0i] = hb.x;  g_vt_hi[v0i + SQ] = hb.y;
                    g_vt_lo[v0i] = lb.x;  g_vt_lo[v0i + SQ] = lb.y;
                }
            }
        }
    }
}

// ---------------- 4) flash attention, bf16x3 tensor ----------------
// CTA = (qblock of 128, bh). 8 warps, warp owns 16 q-rows. KV tiles of 64.
__global__ __launch_bounds__(256) void attn_kernel(const float* __restrict__ adj,
                                                   float* __restrict__ hout) {
    __shared__ __nv_bfloat16 Kh[64][72], Kl[64][72], Vh[64][72], Vl[64][72];
    const int bh = blockIdx.y;
    const int b = bh >> 4, h = bh & 15;
    const int qb = blockIdx.x;
    const int tid = threadIdx.x;
    const int warp = tid >> 5, lane = tid & 31, g = lane >> 2, tg = lane & 3;
    const int qrow = qb * 128 + warp * 16 + g;   // rows qrow (c0,c1) and qrow+8 (c2,c3)

    // Q fragments (resident whole kernel)
    uint32_t qhA[4][4], qlA[4][4];
    {
        const __nv_bfloat16* qh = g_q_hi + (size_t)bh * SQ * HD;
        const __nv_bfloat16* ql = g_q_lo + (size_t)bh * SQ * HD;
        #pragma unroll
        for (int kt = 0; kt < 4; kt++) {
            int c = kt * 16 + 2 * tg;
            qhA[kt][0] = *(const uint32_t*)(qh + (size_t)qrow * HD + c);
            qhA[kt][1] = *(const uint32_t*)(qh + (size_t)(qrow + 8) * HD + c);
            qhA[kt][2] = *(const uint32_t*)(qh + (size_t)qrow * HD + c + 8);
            qhA[kt][3] = *(const uint32_t*)(qh + (size_t)(qrow + 8) * HD + c + 8);
            qlA[kt][0] = *(const uint32_t*)(ql + (size_t)qrow * HD + c);
            qlA[kt][1] = *(const uint32_t*)(ql + (size_t)(qrow + 8) * HD + c);
            qlA[kt][2] = *(const uint32_t*)(ql + (size_t)qrow * HD + c + 8);
            qlA[kt][3] = *(const uint32_t*)(ql + (size_t)(qrow + 8) * HD + c + 8);
        }
    }

    float o[8][4];
    #pragma unroll
    for (int i = 0; i < 8; i++)
        #pragma unroll
        for (int j = 0; j < 4; j++) o[i][j] = 0.0f;
    float mr0 = -1e30f, mr1 = -1e30f, l0 = 0.0f, l1 = 0.0f;

    const float* adjr0 = adj + ((size_t)b * SQ + qrow) * SQ;
    const float* adjr1 = adjr0 + 8 * SQ;

    for (int kv0 = 0; kv0 < SQ; kv0 += 64) {
        __syncthreads();
        #pragma unroll
        for (int c = tid; c < 512; c += 256) {
            int r = c >> 3, cc = (c & 7) * 8;
            *(uint4*)&Kh[r][cc] = *(const uint4*)(g_k_hi + ((size_t)bh * SQ + kv0 + r) * HD + cc);
            *(uint4*)&Kl[r][cc] = *(const uint4*)(g_k_lo + ((size_t)bh * SQ + kv0 + r) * HD + cc);
            *(uint4*)&Vh[r][cc] = *(const uint4*)(g_vt_hi + ((size_t)bh * HD + r) * SQ + kv0 + cc);
            *(uint4*)&Vl[r][cc] = *(const uint4*)(g_vt_lo + ((size_t)bh * HD + r) * SQ + kv0 + cc);
        }
        __syncthreads();

        // S = Q K^T (bf16x3)
        float s[8][4];
        #pragma unroll
        for (int i = 0; i < 8; i++)
            #pragma unroll
            for (int j = 0; j < 4; j++) s[i][j] = 0.0f;
        #pragma unroll
        for (int nt = 0; nt < 8; nt++) {
            int rn = nt * 8 + g;
            #pragma unroll
            for (int kt = 0; kt < 4; kt++) {
                int c = kt * 16 + 2 * tg;
                uint32_t b0h = *(uint32_t*)&Kh[rn][c];
                uint32_t b1h = *(uint32_t*)&Kh[rn][c + 8];
                uint32_t b0l = *(uint32_t*)&Kl[rn][c];
                uint32_t b1l = *(uint32_t*)&Kl[rn][c + 8];
                mma_bf16(s[nt], qhA[kt], b0h, b1h);
                mma_bf16(s[nt], qhA[kt], b0l, b1l);
                mma_bf16(s[nt], qlA[kt], b0h, b1h);
            }
        }

        // scale + adjacency mask
        #pragma unroll
        for (int nt = 0; nt < 8; nt++) {
            int col = kv0 + nt * 8 + 2 * tg;
            float2 a0 = *(const float2*)(adjr0 + col);
            float2 a1 = *(const float2*)(adjr1 + col);
            s[nt][0] = s[nt][0] * 0.125f + (a0.x < 0.5f ? NEGMASK : 0.0f);
            s[nt][1] = s[nt][1] * 0.125f + (a0.y < 0.5f ? NEGMASK : 0.0f);
            s[nt][2] = s[nt][2] * 0.125f + (a1.x < 0.5f ? NEGMASK : 0.0f);
            s[nt][3] = s[nt][3] * 0.125f + (a1.y < 0.5f ? NEGMASK : 0.0f);
        }

        // row maxima (4-lane bfly within quad groups)
        float mx0 = -1e30f, mx1 = -1e30f;
        #pragma unroll
        for (int nt = 0; nt < 8; nt++) {
            mx0 = fmaxf(mx0, fmaxf(s[nt][0], s[nt][1]));
            mx1 = fmaxf(mx1, fmaxf(s[nt][2], s[nt][3]));
        }
        mx0 = fmaxf(mx0, __shfl_xor_sync(0xffffffff, mx0, 1));
        mx0 = fmaxf(mx0, __shfl_xor_sync(0xffffffff, mx0, 2));
        mx1 = fmaxf(mx1, __shfl_xor_sync(0xffffffff, mx1, 1));
        mx1 = fmaxf(mx1, __shfl_xor_sync(0xffffffff, mx1, 2));
        float nm0 = fmaxf(mr0, mx0), nm1 = fmaxf(mr1, mx1);
        float corr0 = __expf(mr0 - nm0), corr1 = __expf(mr1 - nm1);
        mr0 = nm0; mr1 = nm1;

        // probs -> bf16 hi/lo A-fragments (direct C->A layout identity), row sums
        float ps0 = 0.0f, ps1 = 0.0f;
        uint32_t phA[4][4], plA[4][4];
        #pragma unroll
        for (int nt = 0; nt < 8; nt++) {
            float p0 = __expf(s[nt][0] - nm0);
            float p1 = __expf(s[nt][1] - nm0);
            float p2 = __expf(s[nt][2] - nm1);
            float p3 = __expf(s[nt][3] - nm1);
            ps0 += p0 + p1;  ps1 += p2 + p3;
            int kt = nt >> 1;
            if ((nt & 1) == 0) {
                split2(p0, p1, phA[kt][0], plA[kt][0]);
                split2(p2, p3, phA[kt][1], plA[kt][1]);
            } else {
                split2(p0, p1, phA[kt][2], plA[kt][2]);
                split2(p2, p3, phA[kt][3], plA[kt][3]);
            }
        }
        ps0 += __shfl_xor_sync(0xffffffff, ps0, 1);
        ps0 += __shfl_xor_sync(0xffffffff, ps0, 2);
        ps1 += __shfl_xor_sync(0xffffffff, ps1, 1);
        ps1 += __shfl_xor_sync(0xffffffff, ps1, 2);
        l0 = l0 * corr0 + ps0;
        l1 = l1 * corr1 + ps1;

        // rescale O, then O += P V (bf16x3)
        #pragma unroll
        for (int nt = 0; nt < 8; nt++) {
            o[nt][0] *= corr0; o[nt][1] *= corr0;
            o[nt][2] *= corr1; o[nt][3] *= corr1;
        }
        #pragma unroll
        for (int nt = 0; nt < 8; nt++) {
            int rn = nt * 8 + g;
            #pragma unroll
            for (int kt = 0; kt < 4; kt++) {
                int c = kt * 16 + 2 * tg;
                uint32_t v0h = *(uint32_t*)&Vh[rn][c];
                uint32_t v1h = *(uint32_t*)&Vh[rn][c + 8];
                uint32_t v0l = *(uint32_t*)&Vl[rn][c];
                uint32_t v1l = *(uint32_t*)&Vl[rn][c + 8];
                mma_bf16(o[nt], phA[kt], v0h, v1h);
                mma_bf16(o[nt], phA[kt], v0l, v1l);
                mma_bf16(o[nt], plA[kt], v0h, v1h);
            }
        }
    }

    // epilogue: /l, relu, store
    float inv0 = 1.0f / l0, inv1 = 1.0f / l1;
    #pragma unroll
    for (int nt = 0; nt < 8; nt++) {
        int hd = nt * 8 + 2 * tg;
        float2 r0, r1;
        r0.x = fmaxf(o[nt][0] * inv0, 0.0f);
        r0.y = fmaxf(o[nt][1] * inv0, 0.0f);
        r1.x = fmaxf(o[nt][2] * inv1, 0.0f);
        r1.y = fmaxf(o[nt][3] * inv1, 0.0f);
        *(float2*)(hout + ((size_t)b * SQ + qrow) * DIM + h * HD + hd) = r0;
        *(float2*)(hout + ((size_t)b * SQ + qrow + 8) * DIM + h * HD + hd) = r1;
    }
}

// ---------------- launch ----------------
extern "C" void kernel_launch(void* const* d_in, const int* in_sizes, int n_in,
                              void* d_out, int out_size) {
    const float* x   = (const float*)d_in[0];
    const float* adj = (const float*)d_in[1];
    const float* Wq  = (const float*)d_in[2];
    const float* bq  = (const float*)d_in[3];
    const float* Wk  = (const float*)d_in[4];
    const float* bk  = (const float*)d_in[5];
    const float* Wv  = (const float*)d_in[6];
    const float* bv  = (const float*)d_in[7];

    float* hout   = (float*)d_out;
    float* adjout = (float*)d_out + (size_t)BN * SQ * DIM;

    split_x_kernel<<<(BN * SQ * DIM) / (256 * 4), 256>>>(x);
    split_w_kernel<<<dim3(DIM / 32, DIM / 32, 3), dim3(32, 8)>>>(Wq, Wk, Wv);
    qkv_gemm<<<dim3(DIM / 128, (BN * SQ) / 128, 3), 256>>>(bq, bk, bv);
    attn_kernel<<<dim3(SQ / 128, BH), 256>>>(adj, hout);
    cudaMemcpyAsync(adjout, adj, (size_t)BN * SQ * SQ * sizeof(float),
                    cudaMemcpyDeviceToDevice);
}

// round 5
// speedup vs baseline: 4.7864x; 1.2545x over previous
#include <cuda_runtime.h>
#include <cuda_bf16.h>
#include <cstdint>

#define BN 4
#define SQ 1024
#define DIM 1024
#define NH 16
#define HD 64
#define BH (BN*NH)
#define NEGMASK (-10000000.0f)

// ---------------- scratch (device globals; no allocs allowed) ----------------
__device__ __nv_bfloat16 g_x_hi[BN*SQ*DIM];
__device__ __nv_bfloat16 g_x_lo[BN*SQ*DIM];
__device__ __nv_bfloat16 g_wt_hi[3*DIM*DIM];   // W^T  [n][k]
__device__ __nv_bfloat16 g_wt_lo[3*DIM*DIM];
__device__ __nv_bfloat16 g_q_hi[BH*SQ*HD];
__device__ __nv_bfloat16 g_q_lo[BH*SQ*HD];
__device__ __nv_bfloat16 g_k_hi[BH*SQ*HD];
__device__ __nv_bfloat16 g_k_lo[BH*SQ*HD];
__device__ __nv_bfloat16 g_vt_hi[BH*HD*SQ];    // V^T  [bh][hd][s]
__device__ __nv_bfloat16 g_vt_lo[BH*HD*SQ];

// ---------------- helpers ----------------
__device__ __forceinline__ void split2(float a, float b, uint32_t& hi, uint32_t& lo) {
    __nv_bfloat162 h = __floats2bfloat162_rn(a, b);
    float ra = a - __bfloat162float(h.x);
    float rb = b - __bfloat162float(h.y);
    __nv_bfloat162 l = __floats2bfloat162_rn(ra, rb);
    hi = *reinterpret_cast<uint32_t*>(&h);
    lo = *reinterpret_cast<uint32_t*>(&l);
}

__device__ __forceinline__ void mma_bf16(float* c, const uint32_t* a, uint32_t b0, uint32_t b1) {
    asm volatile(
        "mma.sync.aligned.m16n8k16.row.col.f32.bf16.bf16.f32 "
        "{%0,%1,%2,%3}, {%4,%5,%6,%7}, {%8,%9}, {%0,%1,%2,%3};\n"
        : "+f"(c[0]), "+f"(c[1]), "+f"(c[2]), "+f"(c[3])
        : "r"(a[0]), "r"(a[1]), "r"(a[2]), "r"(a[3]), "r"(b0), "r"(b1));
}

__device__ __forceinline__ void cp16(__nv_bfloat16* dst_smem, const __nv_bfloat16* src) {
    uint32_t d = (uint32_t)__cvta_generic_to_shared(dst_smem);
    asm volatile("cp.async.cg.shared.global [%0], [%1], 16;\n" :: "r"(d), "l"(src));
}
#define CP_COMMIT() asm volatile("cp.async.commit_group;\n")
#define CP_WAIT1()  asm volatile("cp.async.wait_group 1;\n")
#define CP_WAIT0()  asm volatile("cp.async.wait_group 0;\n")

// ---------------- 1) split x into bf16 hi/lo ----------------
__global__ void split_x_kernel(const float* __restrict__ x) {
    size_t i = ((size_t)blockIdx.x * 256 + threadIdx.x) * 4;
    float4 v = *(const float4*)(x + i);
    uint32_t h0, l0, h1, l1;
    split2(v.x, v.y, h0, l0);
    split2(v.z, v.w, h1, l1);
    uint2 hh; hh.x = h0; hh.y = h1;
    uint2 ll; ll.x = l0; ll.y = l1;
    *(uint2*)(g_x_hi + i) = hh;
    *(uint2*)(g_x_lo + i) = ll;
}

// ---------------- 2) transpose + split W -> Wt[n][k] hi/lo ----------------
__global__ void split_w_kernel(const float* __restrict__ Wq,
                               const float* __restrict__ Wk,
                               const float* __restrict__ Wv) {
    __shared__ float t[32][33];
    int z = blockIdx.z;
    const float* W = (z == 0) ? Wq : (z == 1) ? Wk : Wv;
    __nv_bfloat16* wth = g_wt_hi + (size_t)z * DIM * DIM;
    __nv_bfloat16* wtl = g_wt_lo + (size_t)z * DIM * DIM;
    int n0 = blockIdx.x * 32, k0 = blockIdx.y * 32;
    int tx = threadIdx.x, ty = threadIdx.y;
    #pragma unroll
    for (int r = 0; r < 4; r++)
        t[ty + 8 * r][tx] = W[(size_t)(k0 + ty + 8 * r) * DIM + n0 + tx];
    __syncthreads();
    #pragma unroll
    for (int r = 0; r < 4; r++) {
        float v = t[tx][ty + 8 * r];
        size_t idx = (size_t)(n0 + ty + 8 * r) * DIM + k0 + tx;
        __nv_bfloat16 hb = __float2bfloat16(v);
        wth[idx] = hb;
        wtl[idx] = __float2bfloat16(v - __bfloat162float(hb));
    }
}

// ---------------- 3) QKV GEMM: bf16x3 tensor, 128x128 CTA tile ----------------
// cp.async double-buffered k-stages of 32; 2 CTAs/SM.
#define QSTG (128*40)
__global__ __launch_bounds__(256, 2) void qkv_gemm(const float* __restrict__ bq,
                                                   const float* __restrict__ bk,
                                                   const float* __restrict__ bv) {
    extern __shared__ __nv_bfloat16 smq[];
    const int z = blockIdx.z;
    const __nv_bfloat16* wth = g_wt_hi + (size_t)z * DIM * DIM;
    const __nv_bfloat16* wtl = g_wt_lo + (size_t)z * DIM * DIM;
    const float* bias = (z == 0) ? bq : (z == 1) ? bk : bv;
    const int m0 = blockIdx.y * 128, n0 = blockIdx.x * 128;
    const int tid = threadIdx.x;
    const int warp = tid >> 5, lane = tid & 31, g = lane >> 2, tg = lane & 3;
    const int wy = warp >> 2, wx = warp & 3;

    // loader: per stage, 4 arrays of [128][32] bf16, row stride 40
    const int lr = tid >> 1;              // row 0..127
    const int lcc = (tid & 1) * 16;       // col chunk 0 / 16

    float acc[4][4][4];
    #pragma unroll
    for (int a = 0; a < 4; a++)
        #pragma unroll
        for (int b = 0; b < 4; b++)
            #pragma unroll
            for (int c = 0; c < 4; c++) acc[a][b][c] = 0.0f;

    // prologue: stage 0
    {
        __nv_bfloat16* st = smq;
        size_t xo = (size_t)(m0 + lr) * DIM + 0 + lcc;
        size_t wo = (size_t)(n0 + lr) * DIM + 0 + lcc;
        __nv_bfloat16* dst = st + lr * 40 + lcc;
        cp16(dst,              g_x_hi + xo);  cp16(dst + 8,              g_x_hi + xo + 8);
        cp16(dst + QSTG,       g_x_lo + xo);  cp16(dst + QSTG + 8,       g_x_lo + xo + 8);
        cp16(dst + 2 * QSTG,   wth + wo);     cp16(dst + 2 * QSTG + 8,   wth + wo + 8);
        cp16(dst + 3 * QSTG,   wtl + wo);     cp16(dst + 3 * QSTG + 8,   wtl + wo + 8);
        CP_COMMIT();
    }

    for (int it = 0; it < DIM / 32; it++) {
        const int cur = it & 1;
        const int k0 = it * 32;
        if (k0 + 32 < DIM) {
            __nv_bfloat16* st = smq + (cur ^ 1) * 4 * QSTG;
            size_t xo = (size_t)(m0 + lr) * DIM + k0 + 32 + lcc;
            size_t wo = (size_t)(n0 + lr) * DIM + k0 + 32 + lcc;
            __nv_bfloat16* dst = st + lr * 40 + lcc;
            cp16(dst,              g_x_hi + xo);  cp16(dst + 8,              g_x_hi + xo + 8);
            cp16(dst + QSTG,       g_x_lo + xo);  cp16(dst + QSTG + 8,       g_x_lo + xo + 8);
            cp16(dst + 2 * QSTG,   wth + wo);     cp16(dst + 2 * QSTG + 8,   wth + wo + 8);
            cp16(dst + 3 * QSTG,   wtl + wo);     cp16(dst + 3 * QSTG + 8,   wtl + wo + 8);
            CP_COMMIT();
            CP_WAIT1();
        } else {
            CP_WAIT0();
        }
        __syncthreads();

        const __nv_bfloat16* Xh = smq + cur * 4 * QSTG;
        const __nv_bfloat16* Xl = Xh + QSTG;
        const __nv_bfloat16* Wh = Xh + 2 * QSTG;
        const __nv_bfloat16* Wl = Xh + 3 * QSTG;

        #pragma unroll
        for (int kt = 0; kt < 2; kt++) {
            uint32_t ah[4][4], al[4][4];
            const int cI = kt * 16 + 2 * tg;
            #pragma unroll
            for (int mt = 0; mt < 4; mt++) {
                int r = wy * 64 + mt * 16;
                ah[mt][0] = *(const uint32_t*)(Xh + (r + g) * 40 + cI);
                ah[mt][1] = *(const uint32_t*)(Xh + (r + g + 8) * 40 + cI);
                ah[mt][2] = *(const uint32_t*)(Xh + (r + g) * 40 + cI + 8);
                ah[mt][3] = *(const uint32_t*)(Xh + (r + g + 8) * 40 + cI + 8);
                al[mt][0] = *(const uint32_t*)(Xl + (r + g) * 40 + cI);
                al[mt][1] = *(const uint32_t*)(Xl + (r + g + 8) * 40 + cI);
                al[mt][2] = *(const uint32_t*)(Xl + (r + g) * 40 + cI + 8);
                al[mt][3] = *(const uint32_t*)(Xl + (r + g + 8) * 40 + cI + 8);
            }
            #pragma unroll
            for (int nt = 0; nt < 4; nt++) {
                int rn = wx * 32 + nt * 8 + g;
                uint32_t bh0 = *(const uint32_t*)(Wh + rn * 40 + cI);
                uint32_t bh1 = *(const uint32_t*)(Wh + rn * 40 + cI + 8);
                uint32_t bl0 = *(const uint32_t*)(Wl + rn * 40 + cI);
                uint32_t bl1 = *(const uint32_t*)(Wl + rn * 40 + cI + 8);
                #pragma unroll
                for (int mt = 0; mt < 4; mt++) {
                    mma_bf16(acc[mt][nt], ah[mt], bh0, bh1);
                    mma_bf16(acc[mt][nt], ah[mt], bl0, bl1);
                    mma_bf16(acc[mt][nt], al[mt], bh0, bh1);
                }
            }
        }
        __syncthreads();
    }

    // epilogue: +bias, split to bf16 hi/lo, scatter to headed layouts
    #pragma unroll
    for (int mt = 0; mt < 4; mt++) {
        #pragma unroll
        for (int nt = 0; nt < 4; nt++) {
            int n = n0 + wx * 32 + nt * 8 + 2 * tg;
            float b0 = bias[n], b1 = bias[n + 1];
            int hh = n >> 6, hd = n & 63;
            #pragma unroll
            for (int half = 0; half < 2; half++) {
                int m = m0 + wy * 64 + mt * 16 + g + half * 8;
                float v0 = acc[mt][nt][half * 2 + 0] + b0;
                float v1 = acc[mt][nt][half * 2 + 1] + b1;
                int bb = m >> 10, s = m & 1023;
                uint32_t hi, lo;
                split2(v0, v1, hi, lo);
                if (z == 0) {
                    size_t base = ((size_t)(bb * NH + hh) * SQ + s) * HD + hd;
                    *(uint32_t*)(g_q_hi + base) = hi;
                    *(uint32_t*)(g_q_lo + base) = lo;
                } else if (z == 1) {
                    size_t base = ((size_t)(bb * NH + hh) * SQ + s) * HD + hd;
                    *(uint32_t*)(g_k_hi + base) = hi;
                    *(uint32_t*)(g_k_lo + base) = lo;
                } else {
                    size_t v0i = ((size_t)(bb * NH + hh) * HD + hd) * SQ + s;
                    __nv_bfloat162 hb = *reinterpret_cast<__nv_bfloat162*>(&hi);
                    __nv_bfloat162 lb = *reinterpret_cast<__nv_bfloat162*>(&lo);
                    g_vt_hi[v0i] = hb.x;  g_vt_hi[v0i + SQ] = hb.y;
                    g_vt_lo[v0i] = lb.x;  g_vt_lo[v0i + SQ] = lb.y;
                }
            }
        }
    }
}

// ---------------- 4) flash attention, bf16x3 tensor ----------------
// cp.async double-buffered KV tiles of 64; 2 CTAs/SM.
#define ASTG (64*72)
__global__ __launch_bounds__(256, 2) void attn_kernel(const float* __restrict__ adj,
                                                      float* __restrict__ hout) {
    extern __shared__ __nv_bfloat16 sma[];
    const int bh = blockIdx.y;
    const int b = bh >> 4, h = bh & 15;
    const int qb = blockIdx.x;
    const int tid = threadIdx.x;
    const int warp = tid >> 5, lane = tid & 31, g = lane >> 2, tg = lane & 3;
    const int qrow = qb * 128 + warp * 16 + g;

    // loader mapping: per stage 4 arrays of [64][64] bf16, row stride 72
    const int lr = tid >> 2;           // row 0..63
    const int lcc = (tid & 3) * 16;    // col chunk

    // prologue: stage 0 (kv0 = 0)
    {
        __nv_bfloat16* st = sma;
        size_t ko = ((size_t)bh * SQ + 0 + lr) * HD + lcc;
        size_t vo = ((size_t)bh * HD + lr) * SQ + 0 + lcc;
        __nv_bfloat16* dst = st + lr * 72 + lcc;
        cp16(dst,            g_k_hi + ko);  cp16(dst + 8,            g_k_hi + ko + 8);
        cp16(dst + ASTG,     g_k_lo + ko);  cp16(dst + ASTG + 8,     g_k_lo + ko + 8);
        cp16(dst + 2 * ASTG, g_vt_hi + vo); cp16(dst + 2 * ASTG + 8, g_vt_hi + vo + 8);
        cp16(dst + 3 * ASTG, g_vt_lo + vo); cp16(dst + 3 * ASTG + 8, g_vt_lo + vo + 8);
        CP_COMMIT();
    }

    // Q fragments (resident whole kernel)
    uint32_t qhA[4][4], qlA[4][4];
    {
        const __nv_bfloat16* qh = g_q_hi + (size_t)bh * SQ * HD;
        const __nv_bfloat16* ql = g_q_lo + (size_t)bh * SQ * HD;
        #pragma unroll
        for (int kt = 0; kt < 4; kt++) {
            int c = kt * 16 + 2 * tg;
            qhA[kt][0] = *(const uint32_t*)(qh + (size_t)qrow * HD + c);
            qhA[kt][1] = *(const uint32_t*)(qh + (size_t)(qrow + 8) * HD + c);
            qhA[kt][2] = *(const uint32_t*)(qh + (size_t)qrow * HD + c + 8);
            qhA[kt][3] = *(const uint32_t*)(qh + (size_t)(qrow + 8) * HD + c + 8);
            qlA[kt][0] = *(const uint32_t*)(ql + (size_t)qrow * HD + c);
            qlA[kt][1] = *(const uint32_t*)(ql + (size_t)(qrow + 8) * HD + c);
            qlA[kt][2] = *(const uint32_t*)(ql + (size_t)qrow * HD + c + 8);
            qlA[kt][3] = *(const uint32_t*)(ql + (size_t)(qrow + 8) * HD + c + 8);
        }
    }

    float o[8][4];
    #pragma unroll
    for (int i = 0; i < 8; i++)
        #pragma unroll
        for (int j = 0; j < 4; j++) o[i][j] = 0.0f;
    float mr0 = -1e30f, mr1 = -1e30f, l0 = 0.0f, l1 = 0.0f;

    const float* adjr0 = adj + ((size_t)b * SQ + qrow) * SQ;
    const float* adjr1 = adjr0 + 8 * SQ;

    for (int it = 0; it < SQ / 64; it++) {
        const int cur = it & 1;
        const int kv0 = it * 64;
        if (kv0 + 64 < SQ) {
            __nv_bfloat16* st = sma + (cur ^ 1) * 4 * ASTG;
            size_t ko = ((size_t)bh * SQ + kv0 + 64 + lr) * HD + lcc;
            size_t vo = ((size_t)bh * HD + lr) * SQ + kv0 + 64 + lcc;
            __nv_bfloat16* dst = st + lr * 72 + lcc;
            cp16(dst,            g_k_hi + ko);  cp16(dst + 8,            g_k_hi + ko + 8);
            cp16(dst + ASTG,     g_k_lo + ko);  cp16(dst + ASTG + 8,     g_k_lo + ko + 8);
            cp16(dst + 2 * ASTG, g_vt_hi + vo); cp16(dst + 2 * ASTG + 8, g_vt_hi + vo + 8);
            cp16(dst + 3 * ASTG, g_vt_lo + vo); cp16(dst + 3 * ASTG + 8, g_vt_lo + vo + 8);
            CP_COMMIT();
            CP_WAIT1();
        } else {
            CP_WAIT0();
        }
        __syncthreads();

        const __nv_bfloat16* Kh = sma + cur * 4 * ASTG;
        const __nv_bfloat16* Kl = Kh + ASTG;
        const __nv_bfloat16* Vh = Kh + 2 * ASTG;
        const __nv_bfloat16* Vl = Kh + 3 * ASTG;

        // S = Q K^T (bf16x3)
        float s[8][4];
        #pragma unroll
        for (int i = 0; i < 8; i++)
            #pragma unroll
            for (int j = 0; j < 4; j++) s[i][j] = 0.0f;
        #pragma unroll
        for (int nt = 0; nt < 8; nt++) {
            int rn = nt * 8 + g;
            #pragma unroll
            for (int kt = 0; kt < 4; kt++) {
                int c = kt * 16 + 2 * tg;
                uint32_t b0h = *(const uint32_t*)(Kh + rn * 72 + c);
                uint32_t b1h = *(const uint32_t*)(Kh + rn * 72 + c + 8);
                uint32_t b0l = *(const uint32_t*)(Kl + rn * 72 + c);
                uint32_t b1l = *(const uint32_t*)(Kl + rn * 72 + c + 8);
                mma_bf16(s[nt], qhA[kt], b0h, b1h);
                mma_bf16(s[nt], qhA[kt], b0l, b1l);
                mma_bf16(s[nt], qlA[kt], b0h, b1h);
            }
        }

        // scale + adjacency mask
        #pragma unroll
        for (int nt = 0; nt < 8; nt++) {
            int col = kv0 + nt * 8 + 2 * tg;
            float2 a0 = *(const float2*)(adjr0 + col);
            float2 a1 = *(const float2*)(adjr1 + col);
            s[nt][0] = s[nt][0] * 0.125f + (a0.x < 0.5f ? NEGMASK : 0.0f);
            s[nt][1] = s[nt][1] * 0.125f + (a0.y < 0.5f ? NEGMASK : 0.0f);
            s[nt][2] = s[nt][2] * 0.125f + (a1.x < 0.5f ? NEGMASK : 0.0f);
            s[nt][3] = s[nt][3] * 0.125f + (a1.y < 0.5f ? NEGMASK : 0.0f);
        }

        // row maxima (quad bfly)
        float mx0 = -1e30f, mx1 = -1e30f;
        #pragma unroll
        for (int nt = 0; nt < 8; nt++) {
            mx0 = fmaxf(mx0, fmaxf(s[nt][0], s[nt][1]));
            mx1 = fmaxf(mx1, fmaxf(s[nt][2], s[nt][3]));
        }
        mx0 = fmaxf(mx0, __shfl_xor_sync(0xffffffff, mx0, 1));
        mx0 = fmaxf(mx0, __shfl_xor_sync(0xffffffff, mx0, 2));
        mx1 = fmaxf(mx1, __shfl_xor_sync(0xffffffff, mx1, 1));
        mx1 = fmaxf(mx1, __shfl_xor_sync(0xffffffff, mx1, 2));
        float nm0 = fmaxf(mr0, mx0), nm1 = fmaxf(mr1, mx1);
        float corr0 = __expf(mr0 - nm0), corr1 = __expf(mr1 - nm1);
        mr0 = nm0; mr1 = nm1;

        // probs -> bf16 hi/lo A-fragments, row sums
        float ps0 = 0.0f, ps1 = 0.0f;
        uint32_t phA[4][4], plA[4][4];
        #pragma unroll
        for (int nt = 0; nt < 8; nt++) {
            float p0 = __expf(s[nt][0] - nm0);
            float p1 = __expf(s[nt][1] - nm0);
            float p2 = __expf(s[nt][2] - nm1);
            float p3 = __expf(s[nt][3] - nm1);
            ps0 += p0 + p1;  ps1 += p2 + p3;
            int kt = nt >> 1;
            if ((nt & 1) == 0) {
                split2(p0, p1, phA[kt][0], plA[kt][0]);
                split2(p2, p3, phA[kt][1], plA[kt][1]);
            } else {
                split2(p0, p1, phA[kt][2], plA[kt][2]);
                split2(p2, p3, phA[kt][3], plA[kt][3]);
            }
        }
        ps0 += __shfl_xor_sync(0xffffffff, ps0, 1);
        ps0 += __shfl_xor_sync(0xffffffff, ps0, 2);
        ps1 += __shfl_xor_sync(0xffffffff, ps1, 1);
        ps1 += __shfl_xor_sync(0xffffffff, ps1, 2);
        l0 = l0 * corr0 + ps0;
        l1 = l1 * corr1 + ps1;

        // rescale O, then O += P V (bf16x3)
        #pragma unroll
        for (int nt = 0; nt < 8; nt++) {
            o[nt][0] *= corr0; o[nt][1] *= corr0;
            o[nt][2] *= corr1; o[nt][3] *= corr1;
        }
        #pragma unroll
        for (int nt = 0; nt < 8; nt++) {
            int rn = nt * 8 + g;
            #pragma unroll
            for (int kt = 0; kt < 4; kt++) {
                int c = kt * 16 + 2 * tg;
                uint32_t v0h = *(const uint32_t*)(Vh + rn * 72 + c);
                uint32_t v1h = *(const uint32_t*)(Vh + rn * 72 + c + 8);
                uint32_t v0l = *(const uint32_t*)(Vl + rn * 72 + c);
                uint32_t v1l = *(const uint32_t*)(Vl + rn * 72 + c + 8);
                mma_bf16(o[nt], phA[kt], v0h, v1h);
                mma_bf16(o[nt], phA[kt], v0l, v1l);
                mma_bf16(o[nt], plA[kt], v0h, v1h);
            }
        }
        __syncthreads();
    }

    // epilogue: /l, relu, store
    float inv0 = 1.0f / l0, inv1 = 1.0f / l1;
    #pragma unroll
    for (int nt = 0; nt < 8; nt++) {
        int hd = nt * 8 + 2 * tg;
        float2 r0, r1;
        r0.x = fmaxf(o[nt][0] * inv0, 0.0f);
        r0.y = fmaxf(o[nt][1] * inv0, 0.0f);
        r1.x = fmaxf(o[nt][2] * inv1, 0.0f);
        r1.y = fmaxf(o[nt][3] * inv1, 0.0f);
        *(float2*)(hout + ((size_t)b * SQ + qrow) * DIM + h * HD + hd) = r0;
        *(float2*)(hout + ((size_t)b * SQ + qrow + 8) * DIM + h * HD + hd) = r1;
    }
}

// ---------------- launch ----------------
extern "C" void kernel_launch(void* const* d_in, const int* in_sizes, int n_in,
                              void* d_out, int out_size) {
    const float* x   = (const float*)d_in[0];
    const float* adj = (const float*)d_in[1];
    const float* Wq  = (const float*)d_in[2];
    const float* bq  = (const float*)d_in[3];
    const float* Wk  = (const float*)d_in[4];
    const float* bk  = (const float*)d_in[5];
    const float* Wv  = (const float*)d_in[6];
    const float* bv  = (const float*)d_in[7];

    float* hout   = (float*)d_out;
    float* adjout = (float*)d_out + (size_t)BN * SQ * DIM;

    const int qsmem = 2 * 4 * QSTG * (int)sizeof(__nv_bfloat16);   // 81920
    const int asmem = 2 * 4 * ASTG * (int)sizeof(__nv_bfloat16);   // 73728
    cudaFuncSetAttribute(qkv_gemm, cudaFuncAttributeMaxDynamicSharedMemorySize, qsmem);
    cudaFuncSetAttribute(attn_kernel, cudaFuncAttributeMaxDynamicSharedMemorySize, asmem);

    split_x_kernel<<<(BN * SQ * DIM) / (256 * 4), 256>>>(x);
    split_w_kernel<<<dim3(DIM / 32, DIM / 32, 3), dim3(32, 8)>>>(Wq, Wk, Wv);
    qkv_gemm<<<dim3(DIM / 128, (BN * SQ) / 128, 3), 256, qsmem>>>(bq, bk, bv);
    attn_kernel<<<dim3(SQ / 128, BH), 256, asmem>>>(adj, hout);
    cudaMemcpyAsync(adjout, adj, (size_t)BN * SQ * SQ * sizeof(float),
                    cudaMemcpyDeviceToDevice);
}

// round 6
// speedup vs baseline: 4.9705x; 1.0385x over previous
#include <cuda_runtime.h>
#include <cuda_bf16.h>
#include <cstdint>

#define BN 4
#define SQ 1024
#define DIM 1024
#define NH 16
#define HD 64
#define BH (BN*NH)
#define NEGMASK (-10000000.0f)

// ---------------- scratch (device globals; no allocs allowed) ----------------
__device__ __nv_bfloat16 g_x_hi[BN*SQ*DIM];
__device__ __nv_bfloat16 g_x_lo[BN*SQ*DIM];
__device__ __nv_bfloat16 g_wt_hi[3*DIM*DIM];   // W^T  [n][k]
__device__ __nv_bfloat16 g_wt_lo[3*DIM*DIM];
__device__ __nv_bfloat16 g_q_hi[BH*SQ*HD];
__device__ __nv_bfloat16 g_q_lo[BH*SQ*HD];
__device__ __nv_bfloat16 g_k_hi[BH*SQ*HD];
__device__ __nv_bfloat16 g_k_lo[BH*SQ*HD];
__device__ __nv_bfloat16 g_vt_hi[BH*HD*SQ];    // V^T  [bh][hd][s]
__device__ __nv_bfloat16 g_vt_lo[BH*HD*SQ];

// ---------------- helpers ----------------
__device__ __forceinline__ void split2(float a, float b, uint32_t& hi, uint32_t& lo) {
    __nv_bfloat162 h = __floats2bfloat162_rn(a, b);
    float ra = a - __bfloat162float(h.x);
    float rb = b - __bfloat162float(h.y);
    __nv_bfloat162 l = __floats2bfloat162_rn(ra, rb);
    hi = *reinterpret_cast<uint32_t*>(&h);
    lo = *reinterpret_cast<uint32_t*>(&l);
}

__device__ __forceinline__ void mma_bf16(float* c, const uint32_t* a, uint32_t b0, uint32_t b1) {
    asm volatile(
        "mma.sync.aligned.m16n8k16.row.col.f32.bf16.bf16.f32 "
        "{%0,%1,%2,%3}, {%4,%5,%6,%7}, {%8,%9}, {%0,%1,%2,%3};\n"
        : "+f"(c[0]), "+f"(c[1]), "+f"(c[2]), "+f"(c[3])
        : "r"(a[0]), "r"(a[1]), "r"(a[2]), "r"(a[3]), "r"(b0), "r"(b1));
}

__device__ __forceinline__ void ldsm4(uint32_t& r0, uint32_t& r1, uint32_t& r2, uint32_t& r3,
                                      const __nv_bfloat16* p) {
    uint32_t a = (uint32_t)__cvta_generic_to_shared(p);
    asm volatile("ldmatrix.sync.aligned.m8n8.x4.shared.b16 {%0,%1,%2,%3}, [%4];\n"
                 : "=r"(r0), "=r"(r1), "=r"(r2), "=r"(r3) : "r"(a));
}

__device__ __forceinline__ void cp16(__nv_bfloat16* dst_smem, const __nv_bfloat16* src) {
    uint32_t d = (uint32_t)__cvta_generic_to_shared(dst_smem);
    asm volatile("cp.async.cg.shared.global [%0], [%1], 16;\n" :: "r"(d), "l"(src));
}
#define CP_COMMIT() asm volatile("cp.async.commit_group;\n")
#define CP_WAIT1()  asm volatile("cp.async.wait_group 1;\n")
#define CP_WAIT0()  asm volatile("cp.async.wait_group 0;\n")

// ---------------- 1) split x into bf16 hi/lo ----------------
__global__ void split_x_kernel(const float* __restrict__ x) {
    size_t i = ((size_t)blockIdx.x * 256 + threadIdx.x) * 4;
    float4 v = *(const float4*)(x + i);
    uint32_t h0, l0, h1, l1;
    split2(v.x, v.y, h0, l0);
    split2(v.z, v.w, h1, l1);
    uint2 hh; hh.x = h0; hh.y = h1;
    uint2 ll; ll.x = l0; ll.y = l1;
    *(uint2*)(g_x_hi + i) = hh;
    *(uint2*)(g_x_lo + i) = ll;
}

// ---------------- 2) transpose + split W -> Wt[n][k] hi/lo ----------------
__global__ void split_w_kernel(const float* __restrict__ Wq,
                               const float* __restrict__ Wk,
                               const float* __restrict__ Wv) {
    __shared__ float t[32][33];
    int z = blockIdx.z;
    const float* W = (z == 0) ? Wq : (z == 1) ? Wk : Wv;
    __nv_bfloat16* wth = g_wt_hi + (size_t)z * DIM * DIM;
    __nv_bfloat16* wtl = g_wt_lo + (size_t)z * DIM * DIM;
    int n0 = blockIdx.x * 32, k0 = blockIdx.y * 32;
    int tx = threadIdx.x, ty = threadIdx.y;
    #pragma unroll
    for (int r = 0; r < 4; r++)
        t[ty + 8 * r][tx] = W[(size_t)(k0 + ty + 8 * r) * DIM + n0 + tx];
    __syncthreads();
    #pragma unroll
    for (int r = 0; r < 4; r++) {
        float v = t[tx][ty + 8 * r];
        size_t idx = (size_t)(n0 + ty + 8 * r) * DIM + k0 + tx;
        __nv_bfloat16 hb = __float2bfloat16(v);
        wth[idx] = hb;
        wtl[idx] = __float2bfloat16(v - __bfloat162float(hb));
    }
}

// ---------------- 3) QKV GEMM: bf16x3 tensor, 128x128 CTA tile ----------------
#define QSTG (128*40)
__global__ __launch_bounds__(256, 2) void qkv_gemm(const float* __restrict__ bq,
                                                   const float* __restrict__ bk,
                                                   const float* __restrict__ bv) {
    extern __shared__ __nv_bfloat16 smq[];
    const int z = blockIdx.z;
    const __nv_bfloat16* wth = g_wt_hi + (size_t)z * DIM * DIM;
    const __nv_bfloat16* wtl = g_wt_lo + (size_t)z * DIM * DIM;
    const float* bias = (z == 0) ? bq : (z == 1) ? bk : bv;
    const int m0 = blockIdx.y * 128, n0 = blockIdx.x * 128;
    const int tid = threadIdx.x;
    const int warp = tid >> 5, lane = tid & 31, g = lane >> 2, tg = lane & 3;
    const int wy = warp >> 2, wx = warp & 3;

    // ldmatrix lane mapping
    const int lt = lane >> 3, lrow = lane & 7;
    // A tiles: t0=(m,c) t1=(m+8,c) t2=(m,c+8) t3=(m+8,c+8)
    const int aRow = (lt & 1) * 8 + lrow;
    const int aCol = (lt >> 1) * 8;
    // B tiles: t0=(n,c) t1=(n,c+8) t2=(n+8,c) t3=(n+8,c+8)
    const int bRow = (lt >> 1) * 8 + lrow;
    const int bCol = (lt & 1) * 8;

    // loader mapping
    const int lr = tid >> 1;
    const int lcc = (tid & 1) * 16;

    float acc[4][4][4];
    #pragma unroll
    for (int a = 0; a < 4; a++)
        #pragma unroll
        for (int b = 0; b < 4; b++)
            #pragma unroll
            for (int c = 0; c < 4; c++) acc[a][b][c] = 0.0f;

    {
        __nv_bfloat16* st = smq;
        size_t xo = (size_t)(m0 + lr) * DIM + lcc;
        size_t wo = (size_t)(n0 + lr) * DIM + lcc;
        __nv_bfloat16* dst = st + lr * 40 + lcc;
        cp16(dst,              g_x_hi + xo);  cp16(dst + 8,              g_x_hi + xo + 8);
        cp16(dst + QSTG,       g_x_lo + xo);  cp16(dst + QSTG + 8,       g_x_lo + xo + 8);
        cp16(dst + 2 * QSTG,   wth + wo);     cp16(dst + 2 * QSTG + 8,   wth + wo + 8);
        cp16(dst + 3 * QSTG,   wtl + wo);     cp16(dst + 3 * QSTG + 8,   wtl + wo + 8);
        CP_COMMIT();
    }

    for (int it = 0; it < DIM / 32; it++) {
        const int cur = it & 1;
        const int k0 = it * 32;
        if (k0 + 32 < DIM) {
            __nv_bfloat16* st = smq + (cur ^ 1) * 4 * QSTG;
            size_t xo = (size_t)(m0 + lr) * DIM + k0 + 32 + lcc;
            size_t wo = (size_t)(n0 + lr) * DIM + k0 + 32 + lcc;
            __nv_bfloat16* dst = st + lr * 40 + lcc;
            cp16(dst,              g_x_hi + xo);  cp16(dst + 8,              g_x_hi + xo + 8);
            cp16(dst + QSTG,       g_x_lo + xo);  cp16(dst + QSTG + 8,       g_x_lo + xo + 8);
            cp16(dst + 2 * QSTG,   wth + wo);     cp16(dst + 2 * QSTG + 8,   wth + wo + 8);
            cp16(dst + 3 * QSTG,   wtl + wo);     cp16(dst + 3 * QSTG + 8,   wtl + wo + 8);
            CP_COMMIT();
            CP_WAIT1();
        } else {
            CP_WAIT0();
        }
        __syncthreads();

        const __nv_bfloat16* Xh = smq + cur * 4 * QSTG;
        const __nv_bfloat16* Xl = Xh + QSTG;
        const __nv_bfloat16* Wh = Xh + 2 * QSTG;
        const __nv_bfloat16* Wl = Xh + 3 * QSTG;

        #pragma unroll
        for (int kt = 0; kt < 2; kt++) {
            const int cI = kt * 16;
            uint32_t ah[4][4], al[4][4];
            #pragma unroll
            for (int mt = 0; mt < 4; mt++) {
                int r = wy * 64 + mt * 16 + aRow;
                ldsm4(ah[mt][0], ah[mt][1], ah[mt][2], ah[mt][3], Xh + r * 40 + cI + aCol);
                ldsm4(al[mt][0], al[mt][1], al[mt][2], al[mt][3], Xl + r * 40 + cI + aCol);
            }
            #pragma unroll
            for (int ntp = 0; ntp < 2; ntp++) {
                int rn = wx * 32 + ntp * 16 + bRow;
                uint32_t h0, h1, h2, h3, q0, q1, q2, q3;
                ldsm4(h0, h1, h2, h3, Wh + rn * 40 + cI + bCol);
                ldsm4(q0, q1, q2, q3, Wl + rn * 40 + cI + bCol);
                #pragma unroll
                for (int mt = 0; mt < 4; mt++) {
                    mma_bf16(acc[mt][2 * ntp],     ah[mt], h0, h1);
                    mma_bf16(acc[mt][2 * ntp],     ah[mt], q0, q1);
                    mma_bf16(acc[mt][2 * ntp],     al[mt], h0, h1);
                    mma_bf16(acc[mt][2 * ntp + 1], ah[mt], h2, h3);
                    mma_bf16(acc[mt][2 * ntp + 1], ah[mt], q2, q3);
                    mma_bf16(acc[mt][2 * ntp + 1], al[mt], h2, h3);
                }
            }
        }
        __syncthreads();
    }

    // epilogue: +bias, split to bf16 hi/lo, scatter to headed layouts
    #pragma unroll
    for (int mt = 0; mt < 4; mt++) {
        #pragma unroll
        for (int nt = 0; nt < 4; nt++) {
            int n = n0 + wx * 32 + nt * 8 + 2 * tg;
            float b0 = bias[n], b1 = bias[n + 1];
            int hh = n >> 6, hd = n & 63;
            #pragma unroll
            for (int half = 0; half < 2; half++) {
                int m = m0 + wy * 64 + mt * 16 + g + half * 8;
                float v0 = acc[mt][nt][half * 2 + 0] + b0;
                float v1 = acc[mt][nt][half * 2 + 1] + b1;
                int bb = m >> 10, s = m & 1023;
                uint32_t hi, lo;
                split2(v0, v1, hi, lo);
                if (z == 0) {
                    size_t base = ((size_t)(bb * NH + hh) * SQ + s) * HD + hd;
                    *(uint32_t*)(g_q_hi + base) = hi;
                    *(uint32_t*)(g_q_lo + base) = lo;
                } else if (z == 1) {
                    size_t base = ((size_t)(bb * NH + hh) * SQ + s) * HD + hd;
                    *(uint32_t*)(g_k_hi + base) = hi;
                    *(uint32_t*)(g_k_lo + base) = lo;
                } else {
                    size_t v0i = ((size_t)(bb * NH + hh) * HD + hd) * SQ + s;
                    __nv_bfloat162 hb = *reinterpret_cast<__nv_bfloat162*>(&hi);
                    __nv_bfloat162 lb = *reinterpret_cast<__nv_bfloat162*>(&lo);
                    g_vt_hi[v0i] = hb.x;  g_vt_hi[v0i + SQ] = hb.y;
                    g_vt_lo[v0i] = lb.x;  g_vt_lo[v0i + SQ] = lb.y;
                }
            }
        }
    }
}

// ---------------- 4) flash attention, bf16x3 tensor ----------------
#define ASTG (64*72)
__global__ __launch_bounds__(256, 2) void attn_kernel(const float* __restrict__ adj,
                                                      float* __restrict__ hout) {
    extern __shared__ __nv_bfloat16 sma[];
    const int bh = blockIdx.y;
    const int b = bh >> 4, h = bh & 15;
    const int qb = blockIdx.x;
    const int tid = threadIdx.x;
    const int warp = tid >> 5, lane = tid & 31, g = lane >> 2, tg = lane & 3;
    const int qrow = qb * 128 + warp * 16 + g;

    // ldmatrix B-tile mapping: t0=(n,c) t1=(n,c+8) t2=(n+8,c) t3=(n+8,c+8)
    const int lt = lane >> 3, lrow = lane & 7;
    const int bRow = (lt >> 1) * 8 + lrow;
    const int bCol = (lt & 1) * 8;

    const int lr = tid >> 2;
    const int lcc = (tid & 3) * 16;

    {
        __nv_bfloat16* st = sma;
        size_t ko = ((size_t)bh * SQ + lr) * HD + lcc;
        size_t vo = ((size_t)bh * HD + lr) * SQ + lcc;
        __nv_bfloat16* dst = st + lr * 72 + lcc;
        cp16(dst,            g_k_hi + ko);  cp16(dst + 8,            g_k_hi + ko + 8);
        cp16(dst + ASTG,     g_k_lo + ko);  cp16(dst + ASTG + 8,     g_k_lo + ko + 8);
        cp16(dst + 2 * ASTG, g_vt_hi + vo); cp16(dst + 2 * ASTG + 8, g_vt_hi + vo + 8);
        cp16(dst + 3 * ASTG, g_vt_lo + vo); cp16(dst + 3 * ASTG + 8, g_vt_lo + vo + 8);
        CP_COMMIT();
    }

    // Q fragments (resident whole kernel)
    uint32_t qhA[4][4], qlA[4][4];
    {
        const __nv_bfloat16* qh = g_q_hi + (size_t)bh * SQ * HD;
        const __nv_bfloat16* ql = g_q_lo + (size_t)bh * SQ * HD;
        #pragma unroll
        for (int kt = 0; kt < 4; kt++) {
            int c = kt * 16 + 2 * tg;
            qhA[kt][0] = *(const uint32_t*)(qh + (size_t)qrow * HD + c);
            qhA[kt][1] = *(const uint32_t*)(qh + (size_t)(qrow + 8) * HD + c);
            qhA[kt][2] = *(const uint32_t*)(qh + (size_t)qrow * HD + c + 8);
            qhA[kt][3] = *(const uint32_t*)(qh + (size_t)(qrow + 8) * HD + c + 8);
            qlA[kt][0] = *(const uint32_t*)(ql + (size_t)qrow * HD + c);
            qlA[kt][1] = *(const uint32_t*)(ql + (size_t)(qrow + 8) * HD + c);
            qlA[kt][2] = *(const uint32_t*)(ql + (size_t)qrow * HD + c + 8);
            qlA[kt][3] = *(const uint32_t*)(ql + (size_t)(qrow + 8) * HD + c + 8);
        }
    }

    float o[8][4];
    #pragma unroll
    for (int i = 0; i < 8; i++)
        #pragma unroll
        for (int j = 0; j < 4; j++) o[i][j] = 0.0f;
    float mr0 = -1e30f, mr1 = -1e30f, l0 = 0.0f, l1 = 0.0f;

    const float* adjr0 = adj + ((size_t)b * SQ + qrow) * SQ;
    const float* adjr1 = adjr0 + 8 * SQ;

    for (int it = 0; it < SQ / 64; it++) {
        const int cur = it & 1;
        const int kv0 = it * 64;
        if (kv0 + 64 < SQ) {
            __nv_bfloat16* st = sma + (cur ^ 1) * 4 * ASTG;
            size_t ko = ((size_t)bh * SQ + kv0 + 64 + lr) * HD + lcc;
            size_t vo = ((size_t)bh * HD + lr) * SQ + kv0 + 64 + lcc;
            __nv_bfloat16* dst = st + lr * 72 + lcc;
            cp16(dst,            g_k_hi + ko);  cp16(dst + 8,            g_k_hi + ko + 8);
            cp16(dst + ASTG,     g_k_lo + ko);  cp16(dst + ASTG + 8,     g_k_lo + ko + 8);
            cp16(dst + 2 * ASTG, g_vt_hi + vo); cp16(dst + 2 * ASTG + 8, g_vt_hi + vo + 8);
            cp16(dst + 3 * ASTG, g_vt_lo + vo); cp16(dst + 3 * ASTG + 8, g_vt_lo + vo + 8);
            CP_COMMIT();
            CP_WAIT1();
        } else {
            CP_WAIT0();
        }
        __syncthreads();

        const __nv_bfloat16* Kh = sma + cur * 4 * ASTG;
        const __nv_bfloat16* Kl = Kh + ASTG;
        const __nv_bfloat16* Vh = Kh + 2 * ASTG;
        const __nv_bfloat16* Vl = Kh + 3 * ASTG;

        // S = Q K^T (bf16x3), B fragments via ldmatrix
        float s[8][4];
        #pragma unroll
        for (int i = 0; i < 8; i++)
            #pragma unroll
            for (int j = 0; j < 4; j++) s[i][j] = 0.0f;
        #pragma unroll
        for (int ntp = 0; ntp < 4; ntp++) {
            #pragma unroll
            for (int kt = 0; kt < 4; kt++) {
                const __nv_bfloat16* ph = Kh + (ntp * 16 + bRow) * 72 + kt * 16 + bCol;
                const __nv_bfloat16* pl = Kl + (ntp * 16 + bRow) * 72 + kt * 16 + bCol;
                uint32_t h0, h1, h2, h3, e0, e1, e2, e3;
                ldsm4(h0, h1, h2, h3, ph);
                ldsm4(e0, e1, e2, e3, pl);
                mma_bf16(s[2 * ntp],     qhA[kt], h0, h1);
                mma_bf16(s[2 * ntp],     qhA[kt], e0, e1);
                mma_bf16(s[2 * ntp],     qlA[kt], h0, h1);
                mma_bf16(s[2 * ntp + 1], qhA[kt], h2, h3);
                mma_bf16(s[2 * ntp + 1], qhA[kt], e2, e3);
                mma_bf16(s[2 * ntp + 1], qlA[kt], h2, h3);
            }
        }

        // scale + adjacency mask
        #pragma unroll
        for (int nt = 0; nt < 8; nt++) {
            int col = kv0 + nt * 8 + 2 * tg;
            float2 a0 = *(const float2*)(adjr0 + col);
            float2 a1 = *(const float2*)(adjr1 + col);
            s[nt][0] = s[nt][0] * 0.125f + (a0.x < 0.5f ? NEGMASK : 0.0f);
            s[nt][1] = s[nt][1] * 0.125f + (a0.y < 0.5f ? NEGMASK : 0.0f);
            s[nt][2] = s[nt][2] * 0.125f + (a1.x < 0.5f ? NEGMASK : 0.0f);
            s[nt][3] = s[nt][3] * 0.125f + (a1.y < 0.5f ? NEGMASK : 0.0f);
        }

        // row maxima (quad bfly)
        float mx0 = -1e30f, mx1 = -1e30f;
        #pragma unroll
        for (int nt = 0; nt < 8; nt++) {
            mx0 = fmaxf(mx0, fmaxf(s[nt][0], s[nt][1]));
            mx1 = fmaxf(mx1, fmaxf(s[nt][2], s[nt][3]));
        }
        mx0 = fmaxf(mx0, __shfl_xor_sync(0xffffffff, mx0, 1));
        mx0 = fmaxf(mx0, __shfl_xor_sync(0xffffffff, mx0, 2));
        mx1 = fmaxf(mx1, __shfl_xor_sync(0xffffffff, mx1, 1));
        mx1 = fmaxf(mx1, __shfl_xor_sync(0xffffffff, mx1, 2));
        float nm0 = fmaxf(mr0, mx0), nm1 = fmaxf(mr1, mx1);
        float corr0 = __expf(mr0 - nm0), corr1 = __expf(mr1 - nm1);
        mr0 = nm0; mr1 = nm1;

        // probs -> bf16 hi/lo A-fragments, row sums
        float ps0 = 0.0f, ps1 = 0.0f;
        uint32_t phA[4][4], plA[4][4];
        #pragma unroll
        for (int nt = 0; nt < 8; nt++) {
            float p0 = __expf(s[nt][0] - nm0);
            float p1 = __expf(s[nt][1] - nm0);
            float p2 = __expf(s[nt][2] - nm1);
            float p3 = __expf(s[nt][3] - nm1);
            ps0 += p0 + p1;  ps1 += p2 + p3;
            int kt = nt >> 1;
            if ((nt & 1) == 0) {
                split2(p0, p1, phA[kt][0], plA[kt][0]);
                split2(p2, p3, phA[kt][1], plA[kt][1]);
            } else {
                split2(p0, p1, phA[kt][2], plA[kt][2]);
                split2(p2, p3, phA[kt][3], plA[kt][3]);
            }
        }
        ps0 += __shfl_xor_sync(0xffffffff, ps0, 1);
        ps0 += __shfl_xor_sync(0xffffffff, ps0, 2);
        ps1 += __shfl_xor_sync(0xffffffff, ps1, 1);
        ps1 += __shfl_xor_sync(0xffffffff, ps1, 2);
        l0 = l0 * corr0 + ps0;
        l1 = l1 * corr1 + ps1;

        // rescale O, then O += P V (bf16x3), V fragments via ldmatrix
        #pragma unroll
        for (int nt = 0; nt < 8; nt++) {
            o[nt][0] *= corr0; o[nt][1] *= corr0;
            o[nt][2] *= corr1; o[nt][3] *= corr1;
        }
        #pragma unroll
        for (int ntp = 0; ntp < 4; ntp++) {
            #pragma unroll
            for (int kt = 0; kt < 4; kt++) {
                const __nv_bfloat16* ph = Vh + (ntp * 16 + bRow) * 72 + kt * 16 + bCol;
                const __nv_bfloat16* pl = Vl + (ntp * 16 + bRow) * 72 + kt * 16 + bCol;
                uint32_t h0, h1, h2, h3, e0, e1, e2, e3;
                ldsm4(h0, h1, h2, h3, ph);
                ldsm4(e0, e1, e2, e3, pl);
                mma_bf16(o[2 * ntp],     phA[kt], h0, h1);
                mma_bf16(o[2 * ntp],     phA[kt], e0, e1);
                mma_bf16(o[2 * ntp],     plA[kt], h0, h1);
                mma_bf16(o[2 * ntp + 1], phA[kt], h2, h3);
                mma_bf16(o[2 * ntp + 1], phA[kt], e2, e3);
                mma_bf16(o[2 * ntp + 1], plA[kt], h2, h3);
            }
        }
        __syncthreads();
    }

    // epilogue: /l, relu, store
    float inv0 = 1.0f / l0, inv1 = 1.0f / l1;
    #pragma unroll
    for (int nt = 0; nt < 8; nt++) {
        int hd = nt * 8 + 2 * tg;
        float2 r0, r1;
        r0.x = fmaxf(o[nt][0] * inv0, 0.0f);
        r0.y = fmaxf(o[nt][1] * inv0, 0.0f);
        r1.x = fmaxf(o[nt][2] * inv1, 0.0f);
        r1.y = fmaxf(o[nt][3] * inv1, 0.0f);
        *(float2*)(hout + ((size_t)b * SQ + qrow) * DIM + h * HD + hd) = r0;
        *(float2*)(hout + ((size_t)b * SQ + qrow + 8) * DIM + h * HD + hd) = r1;
    }
}

// ---------------- launch ----------------
extern "C" void kernel_launch(void* const* d_in, const int* in_sizes, int n_in,
                              void* d_out, int out_size) {
    const float* x   = (const float*)d_in[0];
    const float* adj = (const float*)d_in[1];
    const float* Wq  = (const float*)d_in[2];
    const float* bq  = (const float*)d_in[3];
    const float* Wk  = (const float*)d_in[4];
    const float* bk  = (const float*)d_in[5];
    const float* Wv  = (const float*)d_in[6];
    const float* bv  = (const float*)d_in[7];

    float* hout   = (float*)d_out;
    float* adjout = (float*)d_out + (size_t)BN * SQ * DIM;

    const int qsmem = 2 * 4 * QSTG * (int)sizeof(__nv_bfloat16);   // 81920
    const int asmem = 2 * 4 * ASTG * (int)sizeof(__nv_bfloat16);   // 73728
    cudaFuncSetAttribute(qkv_gemm, cudaFuncAttributeMaxDynamicSharedMemorySize, qsmem);
    cudaFuncSetAttribute(attn_kernel, cudaFuncAttributeMaxDynamicSharedMemorySize, asmem);

    split_x_kernel<<<(BN * SQ * DIM) / (256 * 4), 256>>>(x);
    split_w_kernel<<<dim3(DIM / 32, DIM / 32, 3), dim3(32, 8)>>>(Wq, Wk, Wv);
    qkv_gemm<<<dim3(DIM / 128, (BN * SQ) / 128, 3), 256, qsmem>>>(bq, bk, bv);
    attn_kernel<<<dim3(SQ / 128, BH), 256, asmem>>>(adj, hout);
    cudaMemcpyAsync(adjout, adj, (size_t)BN * SQ * SQ * sizeof(float),
                    cudaMemcpyDeviceToDevice);
}

// round 8
// speedup vs baseline: 5.2208x; 1.0504x over previous
#include <cuda_runtime.h>
#include <cuda_bf16.h>
#include <cstdint>

#define BN 4
#define SQ 1024
#define DIM 1024
#define NH 16
#define HD 64
#define BH (BN*NH)
// masks / scales in exp2 domain: p = 2^(log2e*(q.k/8 + mask))
#define LOG2E 1.44269504f
#define NEG2  (-10000000.0f * 1.44269504f)
#define QSCALE (0.125f * 1.44269504f)

// ---------------- scratch (device globals; no allocs allowed) ----------------
__device__ __nv_bfloat16 g_x_hi[BN*SQ*DIM];
__device__ __nv_bfloat16 g_x_lo[BN*SQ*DIM];
__device__ __nv_bfloat16 g_wt_hi[3*DIM*DIM];   // W^T  [n][k]
__device__ __nv_bfloat16 g_wt_lo[3*DIM*DIM];
__device__ __nv_bfloat16 g_q_hi[BH*SQ*HD];     // Q pre-scaled by 0.125*log2e
__device__ __nv_bfloat16 g_q_lo[BH*SQ*HD];
__device__ __nv_bfloat16 g_k_hi[BH*SQ*HD];
__device__ __nv_bfloat16 g_k_lo[BH*SQ*HD];
__device__ __nv_bfloat16 g_vt_hi[BH*HD*SQ];    // V^T  [bh][hd][s]
__device__ __nv_bfloat16 g_vt_lo[BH*HD*SQ];

// ---------------- helpers ----------------
__device__ __forceinline__ void split2(float a, float b, uint32_t& hi, uint32_t& lo) {
    __nv_bfloat162 h = __floats2bfloat162_rn(a, b);
    float ra = a - __bfloat162float(h.x);
    float rb = b - __bfloat162float(h.y);
    __nv_bfloat162 l = __floats2bfloat162_rn(ra, rb);
    hi = *reinterpret_cast<uint32_t*>(&h);
    lo = *reinterpret_cast<uint32_t*>(&l);
}

__device__ __forceinline__ float ex2(float x) {
    float y;
    asm("ex2.approx.ftz.f32 %0, %1;" : "=f"(y) : "f"(x));
    return y;
}

__device__ __forceinline__ void mma_bf16(float* c, const uint32_t* a, uint32_t b0, uint32_t b1) {
    asm volatile(
        "mma.sync.aligned.m16n8k16.row.col.f32.bf16.bf16.f32 "
        "{%0,%1,%2,%3}, {%4,%5,%6,%7}, {%8,%9}, {%0,%1,%2,%3};\n"
        : "+f"(c[0]), "+f"(c[1]), "+f"(c[2]), "+f"(c[3])
        : "r"(a[0]), "r"(a[1]), "r"(a[2]), "r"(a[3]), "r"(b0), "r"(b1));
}

__device__ __forceinline__ void ldsm4(uint32_t& r0, uint32_t& r1, uint32_t& r2, uint32_t& r3,
                                      const __nv_bfloat16* p) {
    uint32_t a = (uint32_t)__cvta_generic_to_shared(p);
    asm volatile("ldmatrix.sync.aligned.m8n8.x4.shared.b16 {%0,%1,%2,%3}, [%4];\n"
                 : "=r"(r0), "=r"(r1), "=r"(r2), "=r"(r3) : "r"(a));
}

__device__ __forceinline__ void cp16(__nv_bfloat16* dst_smem, const __nv_bfloat16* src) {
    uint32_t d = (uint32_t)__cvta_generic_to_shared(dst_smem);
    asm volatile("cp.async.cg.shared.global [%0], [%1], 16;\n" :: "r"(d), "l"(src));
}
#define CP_COMMIT() asm volatile("cp.async.commit_group;\n")
#define CP_WAIT1()  asm volatile("cp.async.wait_group 1;\n")
#define CP_WAIT0()  asm volatile("cp.async.wait_group 0;\n")

// ---------------- 1) split x into bf16 hi/lo ----------------
__global__ void split_x_kernel(const float* __restrict__ x) {
    size_t i = ((size_t)blockIdx.x * 256 + threadIdx.x) * 4;
    float4 v = *(const float4*)(x + i);
    uint32_t h0, l0, h1, l1;
    split2(v.x, v.y, h0, l0);
    split2(v.z, v.w, h1, l1);
    uint2 hh; hh.x = h0; hh.y = h1;
    uint2 ll; ll.x = l0; ll.y = l1;
    *(uint2*)(g_x_hi + i) = hh;
    *(uint2*)(g_x_lo + i) = ll;
}

// ---------------- 2) transpose + split W -> Wt[n][k] hi/lo ----------------
__global__ void split_w_kernel(const float* __restrict__ Wq,
                               const float* __restrict__ Wk,
                               const float* __restrict__ Wv) {
    __shared__ float t[32][33];
    int z = blockIdx.z;
    const float* W = (z == 0) ? Wq : (z == 1) ? Wk : Wv;
    __nv_bfloat16* wth = g_wt_hi + (size_t)z * DIM * DIM;
    __nv_bfloat16* wtl = g_wt_lo + (size_t)z * DIM * DIM;
    int n0 = blockIdx.x * 32, k0 = blockIdx.y * 32;
    int tx = threadIdx.x, ty = threadIdx.y;
    #pragma unroll
    for (int r = 0; r < 4; r++)
        t[ty + 8 * r][tx] = W[(size_t)(k0 + ty + 8 * r) * DIM + n0 + tx];
    __syncthreads();
    #pragma unroll
    for (int r = 0; r < 4; r++) {
        float v = t[tx][ty + 8 * r];
        size_t idx = (size_t)(n0 + ty + 8 * r) * DIM + k0 + tx;
        __nv_bfloat16 hb = __float2bfloat16(v);
        wth[idx] = hb;
        wtl[idx] = __float2bfloat16(v - __bfloat162float(hb));
    }
}

// ---------------- 3) QKV GEMM: bf16x3 HMMA, 128x128 CTA tile (unchanged) ----------------
#define QSTG (128*40)
__global__ __launch_bounds__(256, 2) void qkv_gemm(const float* __restrict__ bq,
                                                   const float* __restrict__ bk,
                                                   const float* __restrict__ bv) {
    extern __shared__ __nv_bfloat16 smq[];
    const int z = blockIdx.z;
    const __nv_bfloat16* wth = g_wt_hi + (size_t)z * DIM * DIM;
    const __nv_bfloat16* wtl = g_wt_lo + (size_t)z * DIM * DIM;
    const float* bias = (z == 0) ? bq : (z == 1) ? bk : bv;
    const int m0 = blockIdx.y * 128, n0 = blockIdx.x * 128;
    const int tid = threadIdx.x;
    const int warp = tid >> 5, lane = tid & 31, g = lane >> 2, tg = lane & 3;
    const int wy = warp >> 2, wx = warp & 3;

    const int lt = lane >> 3, lrow = lane & 7;
    const int aRow = (lt & 1) * 8 + lrow;
    const int aCol = (lt >> 1) * 8;
    const int bRow = (lt >> 1) * 8 + lrow;
    const int bCol = (lt & 1) * 8;

    const int lr = tid >> 1;
    const int lcc = (tid & 1) * 16;

    float acc[4][4][4];
    #pragma unroll
    for (int a = 0; a < 4; a++)
        #pragma unroll
        for (int b = 0; b < 4; b++)
            #pragma unroll
            for (int c = 0; c < 4; c++) acc[a][b][c] = 0.0f;

    {
        __nv_bfloat16* st = smq;
        size_t xo = (size_t)(m0 + lr) * DIM + lcc;
        size_t wo = (size_t)(n0 + lr) * DIM + lcc;
        __nv_bfloat16* dst = st + lr * 40 + lcc;
        cp16(dst,              g_x_hi + xo);  cp16(dst + 8,              g_x_hi + xo + 8);
        cp16(dst + QSTG,       g_x_lo + xo);  cp16(dst + QSTG + 8,       g_x_lo + xo + 8);
        cp16(dst + 2 * QSTG,   wth + wo);     cp16(dst + 2 * QSTG + 8,   wth + wo + 8);
        cp16(dst + 3 * QSTG,   wtl + wo);     cp16(dst + 3 * QSTG + 8,   wtl + wo + 8);
        CP_COMMIT();
    }

    for (int it = 0; it < DIM / 32; it++) {
        const int cur = it & 1;
        const int k0 = it * 32;
        if (k0 + 32 < DIM) {
            __nv_bfloat16* st = smq + (cur ^ 1) * 4 * QSTG;
            size_t xo = (size_t)(m0 + lr) * DIM + k0 + 32 + lcc;
            size_t wo = (size_t)(n0 + lr) * DIM + k0 + 32 + lcc;
            __nv_bfloat16* dst = st + lr * 40 + lcc;
            cp16(dst,              g_x_hi + xo);  cp16(dst + 8,              g_x_hi + xo + 8);
            cp16(dst + QSTG,       g_x_lo + xo);  cp16(dst + QSTG + 8,       g_x_lo + xo + 8);
            cp16(dst + 2 * QSTG,   wth + wo);     cp16(dst + 2 * QSTG + 8,   wth + wo + 8);
            cp16(dst + 3 * QSTG,   wtl + wo);     cp16(dst + 3 * QSTG + 8,   wtl + wo + 8);
            CP_COMMIT();
            CP_WAIT1();
        } else {
            CP_WAIT0();
        }
        __syncthreads();

        const __nv_bfloat16* Xh = smq + cur * 4 * QSTG;
        const __nv_bfloat16* Xl = Xh + QSTG;
        const __nv_bfloat16* Wh = Xh + 2 * QSTG;
        const __nv_bfloat16* Wl = Xh + 3 * QSTG;

        #pragma unroll
        for (int kt = 0; kt < 2; kt++) {
            const int cI = kt * 16;
            uint32_t ah[4][4], al[4][4];
            #pragma unroll
            for (int mt = 0; mt < 4; mt++) {
                int r = wy * 64 + mt * 16 + aRow;
                ldsm4(ah[mt][0], ah[mt][1], ah[mt][2], ah[mt][3], Xh + r * 40 + cI + aCol);
                ldsm4(al[mt][0], al[mt][1], al[mt][2], al[mt][3], Xl + r * 40 + cI + aCol);
            }
            #pragma unroll
            for (int ntp = 0; ntp < 2; ntp++) {
                int rn = wx * 32 + ntp * 16 + bRow;
                uint32_t h0, h1, h2, h3, q0, q1, q2, q3;
                ldsm4(h0, h1, h2, h3, Wh + rn * 40 + cI + bCol);
                ldsm4(q0, q1, q2, q3, Wl + rn * 40 + cI + bCol);
                #pragma unroll
                for (int mt = 0; mt < 4; mt++) {
                    mma_bf16(acc[mt][2 * ntp],     ah[mt], h0, h1);
                    mma_bf16(acc[mt][2 * ntp],     ah[mt], q0, q1);
                    mma_bf16(acc[mt][2 * ntp],     al[mt], h0, h1);
                    mma_bf16(acc[mt][2 * ntp + 1], ah[mt], h2, h3);
                    mma_bf16(acc[mt][2 * ntp + 1], ah[mt], q2, q3);
                    mma_bf16(acc[mt][2 * ntp + 1], al[mt], h2, h3);
                }
            }
        }
        __syncthreads();
    }

    // epilogue: +bias (Q additionally pre-scaled into exp2 domain), split, scatter
    #pragma unroll
    for (int mt = 0; mt < 4; mt++) {
        #pragma unroll
        for (int nt = 0; nt < 4; nt++) {
            int n = n0 + wx * 32 + nt * 8 + 2 * tg;
            float b0 = bias[n], b1 = bias[n + 1];
            int hh = n >> 6, hd = n & 63;
            #pragma unroll
            for (int half = 0; half < 2; half++) {
                int m = m0 + wy * 64 + mt * 16 + g + half * 8;
                float v0 = acc[mt][nt][half * 2 + 0] + b0;
                float v1 = acc[mt][nt][half * 2 + 1] + b1;
                if (z == 0) { v0 *= QSCALE; v1 *= QSCALE; }
                int bb = m >> 10, s = m & 1023;
                uint32_t hi, lo;
                split2(v0, v1, hi, lo);
                if (z == 0) {
                    size_t base = ((size_t)(bb * NH + hh) * SQ + s) * HD + hd;
                    *(uint32_t*)(g_q_hi + base) = hi;
                    *(uint32_t*)(g_q_lo + base) = lo;
                } else if (z == 1) {
                    size_t base = ((size_t)(bb * NH + hh) * SQ + s) * HD + hd;
                    *(uint32_t*)(g_k_hi + base) = hi;
                    *(uint32_t*)(g_k_lo + base) = lo;
                } else {
                    size_t v0i = ((size_t)(bb * NH + hh) * HD + hd) * SQ + s;
                    __nv_bfloat162 hb = *reinterpret_cast<__nv_bfloat162*>(&hi);
                    __nv_bfloat162 lb = *reinterpret_cast<__nv_bfloat162*>(&lo);
                    g_vt_hi[v0i] = hb.x;  g_vt_hi[v0i + SQ] = hb.y;
                    g_vt_lo[v0i] = lb.x;  g_vt_lo[v0i + SQ] = lb.y;
                }
            }
        }
    }
}

// ---------------- 4) attention: no-rescale softmax, 3-stage pipeline ----------------
#define ASTG (64*72)
#define NTILE (SQ/64)
__global__ __launch_bounds__(256, 2) void attn_kernel(const float* __restrict__ adj,
                                                      float* __restrict__ hout,
                                                      float* __restrict__ adjout) {
    extern __shared__ __nv_bfloat16 sma[];
    const int bh = blockIdx.y;
    const int b = bh >> 4, h = bh & 15;
    const int qb = blockIdx.x;
    const int tid = threadIdx.x;
    const int warp = tid >> 5, lane = tid & 31, g = lane >> 2, tg = lane & 3;
    const int qrow = qb * 128 + warp * 16 + g;

    const int lt = lane >> 3, lrow = lane & 7;
    const int bRow = (lt >> 1) * 8 + lrow;
    const int bCol = (lt & 1) * 8;

    const int lr = tid >> 2;
    const int lcc = (tid & 3) * 16;

    auto load_tile = [&](int t) {
        __nv_bfloat16* st = sma + (t % 3) * 4 * ASTG;
        size_t ko = ((size_t)bh * SQ + t * 64 + lr) * HD + lcc;
        size_t vo = ((size_t)bh * HD + lr) * SQ + t * 64 + lcc;
        __nv_bfloat16* dst = st + lr * 72 + lcc;
        cp16(dst,            g_k_hi + ko);  cp16(dst + 8,            g_k_hi + ko + 8);
        cp16(dst + ASTG,     g_k_lo + ko);  cp16(dst + ASTG + 8,     g_k_lo + ko + 8);
        cp16(dst + 2 * ASTG, g_vt_hi + vo); cp16(dst + 2 * ASTG + 8, g_vt_hi + vo + 8);
        cp16(dst + 3 * ASTG, g_vt_lo + vo); cp16(dst + 3 * ASTG + 8, g_vt_lo + vo + 8);
    };

    load_tile(0); CP_COMMIT();
    load_tile(1); CP_COMMIT();

    // fold the adj pass-through copy into this kernel (32 KB per CTA)
    {
        int flat = blockIdx.y * gridDim.x + blockIdx.x;      // [0, 512)
        const float4* asrc = (const float4*)adj;
        float4* adst = (float4*)adjout;
        size_t base = (size_t)flat * 2048;
        #pragma unroll
        for (int i = tid; i < 2048; i += 256)
            adst[base + i] = asrc[base + i];
    }

    // Q fragments (pre-scaled by 0.125*log2e in qkv epilogue)
    uint32_t qhA[4][4], qlA[4][4];
    {
        const __nv_bfloat16* qh = g_q_hi + (size_t)bh * SQ * HD;
        const __nv_bfloat16* ql = g_q_lo + (size_t)bh * SQ * HD;
        #pragma unroll
        for (int kt = 0; kt < 4; kt++) {
            int c = kt * 16 + 2 * tg;
            qhA[kt][0] = *(const uint32_t*)(qh + (size_t)qrow * HD + c);
            qhA[kt][1] = *(const uint32_t*)(qh + (size_t)(qrow + 8) * HD + c);
            qhA[kt][2] = *(const uint32_t*)(qh + (size_t)qrow * HD + c + 8);
            qhA[kt][3] = *(const uint32_t*)(qh + (size_t)(qrow + 8) * HD + c + 8);
            qlA[kt][0] = *(const uint32_t*)(ql + (size_t)qrow * HD + c);
            qlA[kt][1] = *(const uint32_t*)(ql + (size_t)(qrow + 8) * HD + c);
            qlA[kt][2] = *(const uint32_t*)(ql + (size_t)qrow * HD + c + 8);
            qlA[kt][3] = *(const uint32_t*)(ql + (size_t)(qrow + 8) * HD + c + 8);
        }
    }

    float o[8][4];
    #pragma unroll
    for (int i = 0; i < 8; i++)
        #pragma unroll
        for (int j = 0; j < 4; j++) o[i][j] = 0.0f;
    float l0 = 0.0f, l1 = 0.0f;

    const float* adjr0 = adj + ((size_t)b * SQ + qrow) * SQ;
    const float* adjr1 = adjr0 + 8 * SQ;

    for (int t = 0; t < NTILE; t++) {
        if (t < NTILE - 1) { CP_WAIT1(); } else { CP_WAIT0(); }
        __syncthreads();
        if (t + 2 < NTILE) { load_tile(t + 2); CP_COMMIT(); }

        const __nv_bfloat16* Kh = sma + (t % 3) * 4 * ASTG;
        const __nv_bfloat16* Kl = Kh + ASTG;
        const __nv_bfloat16* Vh = Kh + 2 * ASTG;
        const __nv_bfloat16* Vl = Kh + 3 * ASTG;
        const int kv0 = t * 64;

        // S2 = (log2e/8) * Q K^T  (scale folded into Q)
        float s[8][4];
        #pragma unroll
        for (int i = 0; i < 8; i++)
            #pragma unroll
            for (int j = 0; j < 4; j++) s[i][j] = 0.0f;
        #pragma unroll
        for (int ntp = 0; ntp < 4; ntp++) {
            #pragma unroll
            for (int kt = 0; kt < 4; kt++) {
                const __nv_bfloat16* ph = Kh + (ntp * 16 + bRow) * 72 + kt * 16 + bCol;
                const __nv_bfloat16* pl = Kl + (ntp * 16 + bRow) * 72 + kt * 16 + bCol;
                uint32_t h0, h1, h2, h3, e0, e1, e2, e3;
                ldsm4(h0, h1, h2, h3, ph);
                ldsm4(e0, e1, e2, e3, pl);
                mma_bf16(s[2 * ntp],     qhA[kt], h0, h1);
                mma_bf16(s[2 * ntp],     qhA[kt], e0, e1);
                mma_bf16(s[2 * ntp],     qlA[kt], h0, h1);
                mma_bf16(s[2 * ntp + 1], qhA[kt], h2, h3);
                mma_bf16(s[2 * ntp + 1], qhA[kt], e2, e3);
                mma_bf16(s[2 * ntp + 1], qlA[kt], h2, h3);
            }
        }

        // mask -> p = 2^s2 (no max subtraction: scores bounded), local l accum
        uint32_t phA[4][4], plA[4][4];
        #pragma unroll
        for (int nt = 0; nt < 8; nt++) {
            int col = kv0 + nt * 8 + 2 * tg;
            float2 a0 = *(const float2*)(adjr0 + col);
            float2 a1 = *(const float2*)(adjr1 + col);
            float p0 = ex2(s[nt][0] + (a0.x < 0.5f ? NEG2 : 0.0f));
            float p1 = ex2(s[nt][1] + (a0.y < 0.5f ? NEG2 : 0.0f));
            float p2 = ex2(s[nt][2] + (a1.x < 0.5f ? NEG2 : 0.0f));
            float p3 = ex2(s[nt][3] + (a1.y < 0.5f ? NEG2 : 0.0f));
            l0 += p0 + p1;
            l1 += p2 + p3;
            int kt = nt >> 1;
            if ((nt & 1) == 0) {
                split2(p0, p1, phA[kt][0], plA[kt][0]);
                split2(p2, p3, phA[kt][1], plA[kt][1]);
            } else {
                split2(p0, p1, phA[kt][2], plA[kt][2]);
                split2(p2, p3, phA[kt][3], plA[kt][3]);
            }
        }

        // O += P V (bf16x3)
        #pragma unroll
        for (int ntp = 0; ntp < 4; ntp++) {
            #pragma unroll
            for (int kt = 0; kt < 4; kt++) {
                const __nv_bfloat16* ph = Vh + (ntp * 16 + bRow) * 72 + kt * 16 + bCol;
                const __nv_bfloat16* pl = Vl + (ntp * 16 + bRow) * 72 + kt * 16 + bCol;
                uint32_t h0, h1, h2, h3, e0, e1, e2, e3;
                ldsm4(h0, h1, h2, h3, ph);
                ldsm4(e0, e1, e2, e3, pl);
                mma_bf16(o[2 * ntp],     phA[kt], h0, h1);
                mma_bf16(o[2 * ntp],     phA[kt], e0, e1);
                mma_bf16(o[2 * ntp],     plA[kt], h0, h1);
                mma_bf16(o[2 * ntp + 1], phA[kt], h2, h3);
                mma_bf16(o[2 * ntp + 1], phA[kt], e2, e3);
                mma_bf16(o[2 * ntp + 1], plA[kt], h2, h3);
            }
        }
    }

    // single deferred l-reduction across the quad
    l0 += __shfl_xor_sync(0xffffffff, l0, 1);
    l0 += __shfl_xor_sync(0xffffffff, l0, 2);
    l1 += __shfl_xor_sync(0xffffffff, l1, 1);
    l1 += __shfl_xor_sync(0xffffffff, l1, 2);

    float inv0 = 1.0f / l0, inv1 = 1.0f / l1;
    #pragma unroll
    for (int nt = 0; nt < 8; nt++) {
        int hd = nt * 8 + 2 * tg;
        float2 r0, r1;
        r0.x = fmaxf(o[nt][0] * inv0, 0.0f);
        r0.y = fmaxf(o[nt][1] * inv0, 0.0f);
        r1.x = fmaxf(o[nt][2] * inv1, 0.0f);
        r1.y = fmaxf(o[nt][3] * inv1, 0.0f);
        *(float2*)(hout + ((size_t)b * SQ + qrow) * DIM + h * HD + hd) = r0;
        *(float2*)(hout + ((size_t)b * SQ + qrow + 8) * DIM + h * HD + hd) = r1;
    }
}

// ---------------- launch ----------------
extern "C" void kernel_launch(void* const* d_in, const int* in_sizes, int n_in,
                              void* d_out, int out_size) {
    const float* x   = (const float*)d_in[0];
    const float* adj = (const float*)d_in[1];
    const float* Wq  = (const float*)d_in[2];
    const float* bq  = (const float*)d_in[3];
    const float* Wk  = (const float*)d_in[4];
    const float* bk  = (const float*)d_in[5];
    const float* Wv  = (const float*)d_in[6];
    const float* bv  = (const float*)d_in[7];

    float* hout   = (float*)d_out;
    float* adjout = (float*)d_out + (size_t)BN * SQ * DIM;

    const int qsmem = 2 * 4 * QSTG * (int)sizeof(__nv_bfloat16);   // 81920
    const int asmem = 3 * 4 * ASTG * (int)sizeof(__nv_bfloat16);   // 110592
    cudaFuncSetAttribute(qkv_gemm, cudaFuncAttributeMaxDynamicSharedMemorySize, qsmem);
    cudaFuncSetAttribute(attn_kernel, cudaFuncAttributeMaxDynamicSharedMemorySize, asmem);

    split_x_kernel<<<(BN * SQ * DIM) / (256 * 4), 256>>>(x);
    split_w_kernel<<<dim3(DIM / 32, DIM / 32, 3), dim3(32, 8)>>>(Wq, Wk, Wv);
    qkv_gemm<<<dim3(DIM / 128, (BN * SQ) / 128, 3), 256, qsmem>>>(bq, bk, bv);
    attn_kernel<<<dim3(SQ / 128, BH), 256, asmem>>>(adj, hout, adjout);
}

// round 9
// speedup vs baseline: 6.0161x; 1.1523x over previous
#include <cuda_runtime.h>
#include <cuda_bf16.h>
#include <cuda_fp16.h>
#include <cstdint>

#define BN 4
#define SQ 1024
#define DIM 1024
#define NH 16
#define HD 64
#define BH (BN*NH)
// exp2-domain: p = 2^(log2e*(q.k/8 + mask))
#define NEG2  (-10000000.0f * 1.44269504f)
#define QSCALE (0.125f * 1.44269504f)

// ---------------- scratch (device globals; no allocs allowed) ----------------
__device__ __nv_bfloat16 g_x_hi[BN*SQ*DIM];
__device__ __nv_bfloat16 g_x_lo[BN*SQ*DIM];
__device__ __nv_bfloat16 g_wt_hi[3*DIM*DIM];   // W^T  [n][k]
__device__ __nv_bfloat16 g_wt_lo[3*DIM*DIM];
__device__ __half g_qh[BH*SQ*HD];              // Q fp16, pre-scaled by 0.125*log2e
__device__ __half g_kh[BH*SQ*HD];              // K fp16
__device__ __half g_vth[BH*HD*SQ];             // V^T fp16 hi  [bh][hd][s]
__device__ __half g_vtl[BH*HD*SQ];             // V^T fp16 lo

// ---------------- helpers ----------------
__device__ __forceinline__ void split2(float a, float b, uint32_t& hi, uint32_t& lo) {
    __nv_bfloat162 h = __floats2bfloat162_rn(a, b);
    float ra = a - __bfloat162float(h.x);
    float rb = b - __bfloat162float(h.y);
    __nv_bfloat162 l = __floats2bfloat162_rn(ra, rb);
    hi = *reinterpret_cast<uint32_t*>(&h);
    lo = *reinterpret_cast<uint32_t*>(&l);
}

__device__ __forceinline__ uint32_t packh2(float a, float b) {
    __half2 h = __floats2half2_rn(a, b);
    return *reinterpret_cast<uint32_t*>(&h);
}

__device__ __forceinline__ float ex2(float x) {
    float y;
    asm("ex2.approx.ftz.f32 %0, %1;" : "=f"(y) : "f"(x));
    return y;
}

__device__ __forceinline__ void mma_bf16(float* c, const uint32_t* a, uint32_t b0, uint32_t b1) {
    asm volatile(
        "mma.sync.aligned.m16n8k16.row.col.f32.bf16.bf16.f32 "
        "{%0,%1,%2,%3}, {%4,%5,%6,%7}, {%8,%9}, {%0,%1,%2,%3};\n"
        : "+f"(c[0]), "+f"(c[1]), "+f"(c[2]), "+f"(c[3])
        : "r"(a[0]), "r"(a[1]), "r"(a[2]), "r"(a[3]), "r"(b0), "r"(b1));
}

__device__ __forceinline__ void mma_f16(float* c, const uint32_t* a, uint32_t b0, uint32_t b1) {
    asm volatile(
        "mma.sync.aligned.m16n8k16.row.col.f32.f16.f16.f32 "
        "{%0,%1,%2,%3}, {%4,%5,%6,%7}, {%8,%9}, {%0,%1,%2,%3};\n"
        : "+f"(c[0]), "+f"(c[1]), "+f"(c[2]), "+f"(c[3])
        : "r"(a[0]), "r"(a[1]), "r"(a[2]), "r"(a[3]), "r"(b0), "r"(b1));
}

__device__ __forceinline__ void ldsm4(uint32_t& r0, uint32_t& r1, uint32_t& r2, uint32_t& r3,
                                      const void* p) {
    uint32_t a = (uint32_t)__cvta_generic_to_shared(p);
    asm volatile("ldmatrix.sync.aligned.m8n8.x4.shared.b16 {%0,%1,%2,%3}, [%4];\n"
                 : "=r"(r0), "=r"(r1), "=r"(r2), "=r"(r3) : "r"(a));
}

__device__ __forceinline__ void cp16(void* dst_smem, const void* src) {
    uint32_t d = (uint32_t)__cvta_generic_to_shared(dst_smem);
    asm volatile("cp.async.cg.shared.global [%0], [%1], 16;\n" :: "r"(d), "l"(src));
}
#define CP_COMMIT() asm volatile("cp.async.commit_group;\n")
#define CP_WAIT1()  asm volatile("cp.async.wait_group 1;\n")
#define CP_WAIT0()  asm volatile("cp.async.wait_group 0;\n")

// ---------------- 1) split x into bf16 hi/lo ----------------
__global__ void split_x_kernel(const float* __restrict__ x) {
    size_t i = ((size_t)blockIdx.x * 256 + threadIdx.x) * 4;
    float4 v = *(const float4*)(x + i);
    uint32_t h0, l0, h1, l1;
    split2(v.x, v.y, h0, l0);
    split2(v.z, v.w, h1, l1);
    uint2 hh; hh.x = h0; hh.y = h1;
    uint2 ll; ll.x = l0; ll.y = l1;
    *(uint2*)(g_x_hi + i) = hh;
    *(uint2*)(g_x_lo + i) = ll;
}

// ---------------- 2) transpose + split W -> Wt[n][k] hi/lo ----------------
__global__ void split_w_kernel(const float* __restrict__ Wq,
                               const float* __restrict__ Wk,
                               const float* __restrict__ Wv) {
    __shared__ float t[32][33];
    int z = blockIdx.z;
    const float* W = (z == 0) ? Wq : (z == 1) ? Wk : Wv;
    __nv_bfloat16* wth = g_wt_hi + (size_t)z * DIM * DIM;
    __nv_bfloat16* wtl = g_wt_lo + (size_t)z * DIM * DIM;
    int n0 = blockIdx.x * 32, k0 = blockIdx.y * 32;
    int tx = threadIdx.x, ty = threadIdx.y;
    #pragma unroll
    for (int r = 0; r < 4; r++)
        t[ty + 8 * r][tx] = W[(size_t)(k0 + ty + 8 * r) * DIM + n0 + tx];
    __syncthreads();
    #pragma unroll
    for (int r = 0; r < 4; r++) {
        float v = t[tx][ty + 8 * r];
        size_t idx = (size_t)(n0 + ty + 8 * r) * DIM + k0 + tx;
        __nv_bfloat16 hb = __float2bfloat16(v);
        wth[idx] = hb;
        wtl[idx] = __float2bfloat16(v - __bfloat162float(hb));
    }
}

// ---------------- 3) QKV GEMM: bf16x3 HMMA, 128x128 CTA tile ----------------
#define QSTG (128*40)
__global__ __launch_bounds__(256, 2) void qkv_gemm(const float* __restrict__ bq,
                                                   const float* __restrict__ bk,
                                                   const float* __restrict__ bv) {
    extern __shared__ __nv_bfloat16 smq[];
    const int z = blockIdx.z;
    const __nv_bfloat16* wth = g_wt_hi + (size_t)z * DIM * DIM;
    const __nv_bfloat16* wtl = g_wt_lo + (size_t)z * DIM * DIM;
    const float* bias = (z == 0) ? bq : (z == 1) ? bk : bv;
    const int m0 = blockIdx.y * 128, n0 = blockIdx.x * 128;
    const int tid = threadIdx.x;
    const int warp = tid >> 5, lane = tid & 31, g = lane >> 2, tg = lane & 3;
    const int wy = warp >> 2, wx = warp & 3;

    const int lt = lane >> 3, lrow = lane & 7;
    const int aRow = (lt & 1) * 8 + lrow;
    const int aCol = (lt >> 1) * 8;
    const int bRow = (lt >> 1) * 8 + lrow;
    const int bCol = (lt & 1) * 8;

    const int lr = tid >> 1;
    const int lcc = (tid & 1) * 16;

    float acc[4][4][4];
    #pragma unroll
    for (int a = 0; a < 4; a++)
        #pragma unroll
        for (int b = 0; b < 4; b++)
            #pragma unroll
            for (int c = 0; c < 4; c++) acc[a][b][c] = 0.0f;

    {
        __nv_bfloat16* st = smq;
        size_t xo = (size_t)(m0 + lr) * DIM + lcc;
        size_t wo = (size_t)(n0 + lr) * DIM + lcc;
        __nv_bfloat16* dst = st + lr * 40 + lcc;
        cp16(dst,              g_x_hi + xo);  cp16(dst + 8,              g_x_hi + xo + 8);
        cp16(dst + QSTG,       g_x_lo + xo);  cp16(dst + QSTG + 8,       g_x_lo + xo + 8);
        cp16(dst + 2 * QSTG,   wth + wo);     cp16(dst + 2 * QSTG + 8,   wth + wo + 8);
        cp16(dst + 3 * QSTG,   wtl + wo);     cp16(dst + 3 * QSTG + 8,   wtl + wo + 8);
        CP_COMMIT();
    }

    for (int it = 0; it < DIM / 32; it++) {
        const int cur = it & 1;
        const int k0 = it * 32;
        if (k0 + 32 < DIM) {
            __nv_bfloat16* st = smq + (cur ^ 1) * 4 * QSTG;
            size_t xo = (size_t)(m0 + lr) * DIM + k0 + 32 + lcc;
            size_t wo = (size_t)(n0 + lr) * DIM + k0 + 32 + lcc;
            __nv_bfloat16* dst = st + lr * 40 + lcc;
            cp16(dst,              g_x_hi + xo);  cp16(dst + 8,              g_x_hi + xo + 8);
            cp16(dst + QSTG,       g_x_lo + xo);  cp16(dst + QSTG + 8,       g_x_lo + xo + 8);
            cp16(dst + 2 * QSTG,   wth + wo);     cp16(dst + 2 * QSTG + 8,   wth + wo + 8);
            cp16(dst + 3 * QSTG,   wtl + wo);     cp16(dst + 3 * QSTG + 8,   wtl + wo + 8);
            CP_COMMIT();
            CP_WAIT1();
        } else {
            CP_WAIT0();
        }
        __syncthreads();

        const __nv_bfloat16* Xh = smq + cur * 4 * QSTG;
        const __nv_bfloat16* Xl = Xh + QSTG;
        const __nv_bfloat16* Wh = Xh + 2 * QSTG;
        const __nv_bfloat16* Wl = Xh + 3 * QSTG;

        #pragma unroll
        for (int kt = 0; kt < 2; kt++) {
            const int cI = kt * 16;
            uint32_t ah[4][4], al[4][4];
            #pragma unroll
            for (int mt = 0; mt < 4; mt++) {
                int r = wy * 64 + mt * 16 + aRow;
                ldsm4(ah[mt][0], ah[mt][1], ah[mt][2], ah[mt][3], Xh + r * 40 + cI + aCol);
                ldsm4(al[mt][0], al[mt][1], al[mt][2], al[mt][3], Xl + r * 40 + cI + aCol);
            }
            #pragma unroll
            for (int ntp = 0; ntp < 2; ntp++) {
                int rn = wx * 32 + ntp * 16 + bRow;
                uint32_t h0, h1, h2, h3, q0, q1, q2, q3;
                ldsm4(h0, h1, h2, h3, Wh + rn * 40 + cI + bCol);
                ldsm4(q0, q1, q2, q3, Wl + rn * 40 + cI + bCol);
                #pragma unroll
                for (int mt = 0; mt < 4; mt++) {
                    mma_bf16(acc[mt][2 * ntp],     ah[mt], h0, h1);
                    mma_bf16(acc[mt][2 * ntp],     ah[mt], q0, q1);
                    mma_bf16(acc[mt][2 * ntp],     al[mt], h0, h1);
                    mma_bf16(acc[mt][2 * ntp + 1], ah[mt], h2, h3);
                    mma_bf16(acc[mt][2 * ntp + 1], ah[mt], q2, q3);
                    mma_bf16(acc[mt][2 * ntp + 1], al[mt], h2, h3);
                }
            }
        }
        __syncthreads();
    }

    // epilogue: +bias; Q scaled into exp2 domain; q/k single fp16, v fp16 hi/lo
    #pragma unroll
    for (int mt = 0; mt < 4; mt++) {
        #pragma unroll
        for (int nt = 0; nt < 4; nt++) {
            int n = n0 + wx * 32 + nt * 8 + 2 * tg;
            float b0 = bias[n], b1 = bias[n + 1];
            int hh = n >> 6, hd = n & 63;
            #pragma unroll
            for (int half = 0; half < 2; half++) {
                int m = m0 + wy * 64 + mt * 16 + g + half * 8;
                float v0 = acc[mt][nt][half * 2 + 0] + b0;
                float v1 = acc[mt][nt][half * 2 + 1] + b1;
                int bb = m >> 10, s = m & 1023;
                if (z == 0) {
                    size_t base = ((size_t)(bb * NH + hh) * SQ + s) * HD + hd;
                    *(uint32_t*)(g_qh + base) = packh2(v0 * QSCALE, v1 * QSCALE);
                } else if (z == 1) {
                    size_t base = ((size_t)(bb * NH + hh) * SQ + s) * HD + hd;
                    *(uint32_t*)(g_kh + base) = packh2(v0, v1);
                } else {
                    size_t v0i = ((size_t)(bb * NH + hh) * HD + hd) * SQ + s;
                    __half h0 = __float2half_rn(v0);
                    __half h1 = __float2half_rn(v1);
                    g_vth[v0i]      = h0;
                    g_vth[v0i + SQ] = h1;
                    g_vtl[v0i]      = __float2half_rn(v0 - __half2float(h0));
                    g_vtl[v0i + SQ] = __float2half_rn(v1 - __half2float(h1));
                }
            }
        }
    }
}

// ---------------- 4) attention: fp16, no-rescale softmax, 3-stage pipeline ----------------
#define ASTG (64*72)
#define NTILE (SQ/64)
__global__ __launch_bounds__(256, 2) void attn_kernel(const float* __restrict__ adj,
                                                      float* __restrict__ hout,
                                                      float* __restrict__ adjout) {
    extern __shared__ __half sma[];
    const int bh = blockIdx.y;
    const int b = bh >> 4, h = bh & 15;
    const int qb = blockIdx.x;
    const int tid = threadIdx.x;
    const int warp = tid >> 5, lane = tid & 31, g = lane >> 2, tg = lane & 3;
    const int qrow = qb * 128 + warp * 16 + g;

    const int lt = lane >> 3, lrow = lane & 7;
    const int bRow = (lt >> 1) * 8 + lrow;
    const int bCol = (lt & 1) * 8;

    const int lr = tid >> 2;
    const int lcc = (tid & 3) * 16;

    // per stage: K | Vh | Vl, each [64][72] fp16
    auto load_tile = [&](int t) {
        __half* st = sma + (t % 3) * 3 * ASTG;
        size_t ko = ((size_t)bh * SQ + t * 64 + lr) * HD + lcc;
        size_t vo = ((size_t)bh * HD + lr) * SQ + t * 64 + lcc;
        __half* dst = st + lr * 72 + lcc;
        cp16(dst,            g_kh + ko);   cp16(dst + 8,            g_kh + ko + 8);
        cp16(dst + ASTG,     g_vth + vo);  cp16(dst + ASTG + 8,     g_vth + vo + 8);
        cp16(dst + 2 * ASTG, g_vtl + vo);  cp16(dst + 2 * ASTG + 8, g_vtl + vo + 8);
    };

    load_tile(0); CP_COMMIT();
    load_tile(1); CP_COMMIT();

    // fold adj pass-through copy (32 KB per CTA)
    {
        int flat = blockIdx.y * gridDim.x + blockIdx.x;
        const float4* asrc = (const float4*)adj;
        float4* adst = (float4*)adjout;
        size_t base = (size_t)flat * 2048;
        #pragma unroll
        for (int i = tid; i < 2048; i += 256)
            adst[base + i] = asrc[base + i];
    }

    // Q fragments (fp16, pre-scaled)
    uint32_t qA[4][4];
    {
        const __half* qh = g_qh + (size_t)bh * SQ * HD;
        #pragma unroll
        for (int kt = 0; kt < 4; kt++) {
            int c = kt * 16 + 2 * tg;
            qA[kt][0] = *(const uint32_t*)(qh + (size_t)qrow * HD + c);
            qA[kt][1] = *(const uint32_t*)(qh + (size_t)(qrow + 8) * HD + c);
            qA[kt][2] = *(const uint32_t*)(qh + (size_t)qrow * HD + c + 8);
            qA[kt][3] = *(const uint32_t*)(qh + (size_t)(qrow + 8) * HD + c + 8);
        }
    }

    float o[8][4];
    #pragma unroll
    for (int i = 0; i < 8; i++)
        #pragma unroll
        for (int j = 0; j < 4; j++) o[i][j] = 0.0f;
    float l0 = 0.0f, l1 = 0.0f;

    const float* adjr0 = adj + ((size_t)b * SQ + qrow) * SQ;
    const float* adjr1 = adjr0 + 8 * SQ;

    for (int t = 0; t < NTILE; t++) {
        if (t < NTILE - 1) { CP_WAIT1(); } else { CP_WAIT0(); }
        __syncthreads();
        if (t + 2 < NTILE) { load_tile(t + 2); CP_COMMIT(); }

        const __half* Kh = sma + (t % 3) * 3 * ASTG;
        const __half* Vh = Kh + ASTG;
        const __half* Vl = Kh + 2 * ASTG;
        const int kv0 = t * 64;

        // S2 = Q K^T (fp16 single-term; scale folded into Q)
        float s[8][4];
        #pragma unroll
        for (int i = 0; i < 8; i++)
            #pragma unroll
            for (int j = 0; j < 4; j++) s[i][j] = 0.0f;
        #pragma unroll
        for (int ntp = 0; ntp < 4; ntp++) {
            #pragma unroll
            for (int kt = 0; kt < 4; kt++) {
                uint32_t h0, h1, h2, h3;
                ldsm4(h0, h1, h2, h3, Kh + (ntp * 16 + bRow) * 72 + kt * 16 + bCol);
                mma_f16(s[2 * ntp],     qA[kt], h0, h1);
                mma_f16(s[2 * ntp + 1], qA[kt], h2, h3);
            }
        }

        // mask -> p = 2^s2, pack to fp16 A-fragments, accumulate l
        uint32_t pA[4][4];
        #pragma unroll
        for (int nt = 0; nt < 8; nt++) {
            int col = kv0 + nt * 8 + 2 * tg;
            float2 a0 = *(const float2*)(adjr0 + col);
            float2 a1 = *(const float2*)(adjr1 + col);
            float p0 = ex2(s[nt][0] + (a0.x < 0.5f ? NEG2 : 0.0f));
            float p1 = ex2(s[nt][1] + (a0.y < 0.5f ? NEG2 : 0.0f));
            float p2 = ex2(s[nt][2] + (a1.x < 0.5f ? NEG2 : 0.0f));
            float p3 = ex2(s[nt][3] + (a1.y < 0.5f ? NEG2 : 0.0f));
            l0 += p0 + p1;
            l1 += p2 + p3;
            int kt = nt >> 1;
            if ((nt & 1) == 0) {
                pA[kt][0] = packh2(p0, p1);
                pA[kt][1] = packh2(p2, p3);
            } else {
                pA[kt][2] = packh2(p0, p1);
                pA[kt][3] = packh2(p2, p3);
            }
        }

        // O += P V (p fp16, v hi+lo)
        #pragma unroll
        for (int ntp = 0; ntp < 4; ntp++) {
            #pragma unroll
            for (int kt = 0; kt < 4; kt++) {
                uint32_t vh0, vh1, vh2, vh3, vl0, vl1, vl2, vl3;
                ldsm4(vh0, vh1, vh2, vh3, Vh + (ntp * 16 + bRow) * 72 + kt * 16 + bCol);
                ldsm4(vl0, vl1, vl2, vl3, Vl + (ntp * 16 + bRow) * 72 + kt * 16 + bCol);
                mma_f16(o[2 * ntp],     pA[kt], vh0, vh1);
                mma_f16(o[2 * ntp],     pA[kt], vl0, vl1);
                mma_f16(o[2 * ntp + 1], pA[kt], vh2, vh3);
                mma_f16(o[2 * ntp + 1], pA[kt], vl2, vl3);
            }
        }
    }

    // deferred l-reduction across the quad
    l0 += __shfl_xor_sync(0xffffffff, l0, 1);
    l0 += __shfl_xor_sync(0xffffffff, l0, 2);
    l1 += __shfl_xor_sync(0xffffffff, l1, 1);
    l1 += __shfl_xor_sync(0xffffffff, l1, 2);

    float inv0 = 1.0f / l0, inv1 = 1.0f / l1;
    #pragma unroll
    for (int nt = 0; nt < 8; nt++) {
        int hd = nt * 8 + 2 * tg;
        float2 r0, r1;
        r0.x = fmaxf(o[nt][0] * inv0, 0.0f);
        r0.y = fmaxf(o[nt][1] * inv0, 0.0f);
        r1.x = fmaxf(o[nt][2] * inv1, 0.0f);
        r1.y = fmaxf(o[nt][3] * inv1, 0.0f);
        *(float2*)(hout + ((size_t)b * SQ + qrow) * DIM + h * HD + hd) = r0;
        *(float2*)(hout + ((size_t)b * SQ + qrow + 8) * DIM + h * HD + hd) = r1;
    }
}

// ---------------- launch ----------------
extern "C" void kernel_launch(void* const* d_in, const int* in_sizes, int n_in,
                              void* d_out, int out_size) {
    const float* x   = (const float*)d_in[0];
    const float* adj = (const float*)d_in[1];
    const float* Wq  = (const float*)d_in[2];
    const float* bq  = (const float*)d_in[3];
    const float* Wk  = (const float*)d_in[4];
    const float* bk  = (const float*)d_in[5];
    const float* Wv  = (const float*)d_in[6];
    const float* bv  = (const float*)d_in[7];

    float* hout   = (float*)d_out;
    float* adjout = (float*)d_out + (size_t)BN * SQ * DIM;

    const int qsmem = 2 * 4 * QSTG * (int)sizeof(__nv_bfloat16);   // 81920
    const int asmem = 3 * 3 * ASTG * (int)sizeof(__half);          // 82944
    cudaFuncSetAttribute(qkv_gemm, cudaFuncAttributeMaxDynamicSharedMemorySize, qsmem);
    cudaFuncSetAttribute(attn_kernel, cudaFuncAttributeMaxDynamicSharedMemorySize, asmem);

    split_x_kernel<<<(BN * SQ * DIM) / (256 * 4), 256>>>(x);
    split_w_kernel<<<dim3(DIM / 32, DIM / 32, 3), dim3(32, 8)>>>(Wq, Wk, Wv);
    qkv_gemm<<<dim3(DIM / 128, (BN * SQ) / 128, 3), 256, qsmem>>>(bq, bk, bv);
    attn_kernel<<<dim3(SQ / 128, BH), 256, asmem>>>(adj, hout, adjout);
}

// round 11
// speedup vs baseline: 7.4194x; 1.2333x over previous
#include <cuda_runtime.h>
#include <cuda_bf16.h>
#include <cuda_fp16.h>
#include <cstdint>

#define BN 4
#define SQ 1024
#define DIM 1024
#define NH 16
#define HD 64
#define BH (BN*NH)
// exp2-domain: p = 2^(log2e*(q.k/8 + mask))
#define NEG2  (-10000000.0f * 1.44269504f)
#define QSCALE (0.125f * 1.44269504f)

// ---------------- scratch (device globals; no allocs allowed) ----------------
__device__ __half g_x_hi[BN*SQ*DIM];           // x fp16 hi
__device__ __half g_x_lo[BN*SQ*DIM];           // x fp16 lo (residual)
__device__ __half g_wt[3*DIM*DIM];             // W^T fp16 [n][k]
__device__ __half g_qh[BH*SQ*HD];              // Q fp16, pre-scaled by 0.125*log2e
__device__ __half g_kh[BH*SQ*HD];              // K fp16
__device__ __half g_vth[BH*HD*SQ];             // V^T fp16 hi  [bh][hd][s]
__device__ __half g_vtl[BH*HD*SQ];             // V^T fp16 lo

// ---------------- helpers ----------------
__device__ __forceinline__ uint32_t packh2(float a, float b) {
    __half2 h = __floats2half2_rn(a, b);
    return *reinterpret_cast<uint32_t*>(&h);
}

__device__ __forceinline__ void split2h(float a, float b, uint32_t& hi, uint32_t& lo) {
    __half ha = __float2half_rn(a), hb = __float2half_rn(b);
    __half la = __float2half_rn(a - __half2float(ha));
    __half lb = __float2half_rn(b - __half2float(hb));
    __half2 h; h.x = ha; h.y = hb;
    __half2 l; l.x = la; l.y = lb;
    hi = *reinterpret_cast<uint32_t*>(&h);
    lo = *reinterpret_cast<uint32_t*>(&l);
}

__device__ __forceinline__ float ex2(float x) {
    float y;
    asm("ex2.approx.ftz.f32 %0, %1;" : "=f"(y) : "f"(x));
    return y;
}

__device__ __forceinline__ void mma_f16(float* c, const uint32_t* a, uint32_t b0, uint32_t b1) {
    asm volatile(
        "mma.sync.aligned.m16n8k16.row.col.f32.f16.f16.f32 "
        "{%0,%1,%2,%3}, {%4,%5,%6,%7}, {%8,%9}, {%0,%1,%2,%3};\n"
        : "+f"(c[0]), "+f"(c[1]), "+f"(c[2]), "+f"(c[3])
        : "r"(a[0]), "r"(a[1]), "r"(a[2]), "r"(a[3]), "r"(b0), "r"(b1));
}

__device__ __forceinline__ void ldsm4(uint32_t& r0, uint32_t& r1, uint32_t& r2, uint32_t& r3,
                                      const void* p) {
    uint32_t a = (uint32_t)__cvta_generic_to_shared(p);
    asm volatile("ldmatrix.sync.aligned.m8n8.x4.shared.b16 {%0,%1,%2,%3}, [%4];\n"
                 : "=r"(r0), "=r"(r1), "=r"(r2), "=r"(r3) : "r"(a));
}

__device__ __forceinline__ void cp16(void* dst_smem, const void* src) {
    uint32_t d = (uint32_t)__cvta_generic_to_shared(dst_smem);
    asm volatile("cp.async.cg.shared.global [%0], [%1], 16;\n" :: "r"(d), "l"(src));
}
#define CP_COMMIT() asm volatile("cp.async.commit_group;\n")
#define CP_WAIT1()  asm volatile("cp.async.wait_group 1;\n")
#define CP_WAIT0()  asm volatile("cp.async.wait_group 0;\n")

// ---------------- 1) split x into fp16 hi/lo ----------------
__global__ void split_x_kernel(const float* __restrict__ x) {
    size_t i = ((size_t)blockIdx.x * 256 + threadIdx.x) * 4;
    float4 v = *(const float4*)(x + i);
    uint32_t h0, l0, h1, l1;
    split2h(v.x, v.y, h0, l0);
    split2h(v.z, v.w, h1, l1);
    uint2 hh; hh.x = h0; hh.y = h1;
    uint2 ll; ll.x = l0; ll.y = l1;
    *(uint2*)(g_x_hi + i) = hh;
    *(uint2*)(g_x_lo + i) = ll;
}

// ---------------- 2) transpose W -> Wt[n][k] fp16 ----------------
__global__ void split_w_kernel(const float* __restrict__ Wq,
                               const float* __restrict__ Wk,
                               const float* __restrict__ Wv) {
    __shared__ float t[32][33];
    int z = blockIdx.z;
    const float* W = (z == 0) ? Wq : (z == 1) ? Wk : Wv;
    __half* wt = g_wt + (size_t)z * DIM * DIM;
    int n0 = blockIdx.x * 32, k0 = blockIdx.y * 32;
    int tx = threadIdx.x, ty = threadIdx.y;
    #pragma unroll
    for (int r = 0; r < 4; r++)
        t[ty + 8 * r][tx] = W[(size_t)(k0 + ty + 8 * r) * DIM + n0 + tx];
    __syncthreads();
    #pragma unroll
    for (int r = 0; r < 4; r++) {
        float v = t[tx][ty + 8 * r];
        size_t idx = (size_t)(n0 + ty + 8 * r) * DIM + k0 + tx;
        wt[idx] = __float2half_rn(v);
    }
}

// ---------------- 3) QKV GEMM: fp16 2-term HMMA, 128x128 CTA tile ----------------
#define QSTG (128*40)
__global__ __launch_bounds__(256, 2) void qkv_gemm(const float* __restrict__ bq,
                                                   const float* __restrict__ bk,
                                                   const float* __restrict__ bv) {
    extern __shared__ __half smq[];
    const int z = blockIdx.z;
    const __half* wt = g_wt + (size_t)z * DIM * DIM;
    const float* bias = (z == 0) ? bq : (z == 1) ? bk : bv;
    const int m0 = blockIdx.y * 128, n0 = blockIdx.x * 128;
    const int tid = threadIdx.x;
    const int warp = tid >> 5, lane = tid & 31, g = lane >> 2, tg = lane & 3;
    const int wy = warp >> 2, wx = warp & 3;

    const int lt = lane >> 3, lrow = lane & 7;
    const int aRow = (lt & 1) * 8 + lrow;
    const int aCol = (lt >> 1) * 8;
    const int bRow = (lt >> 1) * 8 + lrow;
    const int bCol = (lt & 1) * 8;

    const int lr = tid >> 1;
    const int lcc = (tid & 1) * 16;

    float acc[4][4][4];
    #pragma unroll
    for (int a = 0; a < 4; a++)
        #pragma unroll
        for (int b = 0; b < 4; b++)
            #pragma unroll
            for (int c = 0; c < 4; c++) acc[a][b][c] = 0.0f;

    {
        __half* st = smq;
        size_t xo = (size_t)(m0 + lr) * DIM + lcc;
        size_t wo = (size_t)(n0 + lr) * DIM + lcc;
        __half* dst = st + lr * 40 + lcc;
        cp16(dst,            g_x_hi + xo);  cp16(dst + 8,            g_x_hi + xo + 8);
        cp16(dst + QSTG,     g_x_lo + xo);  cp16(dst + QSTG + 8,     g_x_lo + xo + 8);
        cp16(dst + 2 * QSTG, wt + wo);      cp16(dst + 2 * QSTG + 8, wt + wo + 8);
        CP_COMMIT();
    }

    for (int it = 0; it < DIM / 32; it++) {
        const int cur = it & 1;
        const int k0 = it * 32;
        if (k0 + 32 < DIM) {
            __half* st = smq + (cur ^ 1) * 3 * QSTG;
            size_t xo = (size_t)(m0 + lr) * DIM + k0 + 32 + lcc;
            size_t wo = (size_t)(n0 + lr) * DIM + k0 + 32 + lcc;
            __half* dst = st + lr * 40 + lcc;
            cp16(dst,            g_x_hi + xo);  cp16(dst + 8,            g_x_hi + xo + 8);
            cp16(dst + QSTG,     g_x_lo + xo);  cp16(dst + QSTG + 8,     g_x_lo + xo + 8);
            cp16(dst + 2 * QSTG, wt + wo);      cp16(dst + 2 * QSTG + 8, wt + wo + 8);
            CP_COMMIT();
            CP_WAIT1();
        } else {
            CP_WAIT0();
        }
        __syncthreads();

        const __half* Xh = smq + cur * 3 * QSTG;
        const __half* Xl = Xh + QSTG;
        const __half* Wh = Xh + 2 * QSTG;

        #pragma unroll
        for (int kt = 0; kt < 2; kt++) {
            const int cI = kt * 16;
            uint32_t ah[4][4], al[4][4];
            #pragma unroll
            for (int mt = 0; mt < 4; mt++) {
                int r = wy * 64 + mt * 16 + aRow;
                ldsm4(ah[mt][0], ah[mt][1], ah[mt][2], ah[mt][3], Xh + r * 40 + cI + aCol);
                ldsm4(al[mt][0], al[mt][1], al[mt][2], al[mt][3], Xl + r * 40 + cI + aCol);
            }
            #pragma unroll
            for (int ntp = 0; ntp < 2; ntp++) {
                int rn = wx * 32 + ntp * 16 + bRow;
                uint32_t h0, h1, h2, h3;
                ldsm4(h0, h1, h2, h3, Wh + rn * 40 + cI + bCol);
                #pragma unroll
                for (int mt = 0; mt < 4; mt++) {
                    mma_f16(acc[mt][2 * ntp],     ah[mt], h0, h1);
                    mma_f16(acc[mt][2 * ntp],     al[mt], h0, h1);
                    mma_f16(acc[mt][2 * ntp + 1], ah[mt], h2, h3);
                    mma_f16(acc[mt][2 * ntp + 1], al[mt], h2, h3);
                }
            }
        }
        __syncthreads();
    }

    // epilogue: +bias; Q scaled into exp2 domain; q/k single fp16, v fp16 hi/lo
    #pragma unroll
    for (int mt = 0; mt < 4; mt++) {
        #pragma unroll
        for (int nt = 0; nt < 4; nt++) {
            int n = n0 + wx * 32 + nt * 8 + 2 * tg;
            float b0 = bias[n], b1 = bias[n + 1];
            int hh = n >> 6, hd = n & 63;
            #pragma unroll
            for (int half = 0; half < 2; half++) {
                int m = m0 + wy * 64 + mt * 16 + g + half * 8;
                float v0 = acc[mt][nt][half * 2 + 0] + b0;
                float v1 = acc[mt][nt][half * 2 + 1] + b1;
                int bb = m >> 10, s = m & 1023;
                if (z == 0) {
                    size_t base = ((size_t)(bb * NH + hh) * SQ + s) * HD + hd;
                    *(uint32_t*)(g_qh + base) = packh2(v0 * QSCALE, v1 * QSCALE);
                } else if (z == 1) {
                    size_t base = ((size_t)(bb * NH + hh) * SQ + s) * HD + hd;
                    *(uint32_t*)(g_kh + base) = packh2(v0, v1);
                } else {
                    size_t v0i = ((size_t)(bb * NH + hh) * HD + hd) * SQ + s;
                    __half h0 = __float2half_rn(v0);
                    __half h1 = __float2half_rn(v1);
                    g_vth[v0i]      = h0;
                    g_vth[v0i + SQ] = h1;
                    g_vtl[v0i]      = __float2half_rn(v0 - __half2float(h0));
                    g_vtl[v0i + SQ] = __float2half_rn(v1 - __half2float(h1));
                }
            }
        }
    }
}

// ---------------- 4) attention: fp16, no-rescale softmax, 3-stage pipeline ----------------
#define ASTG (64*72)
#define NTILE (SQ/64)
__global__ __launch_bounds__(256, 2) void attn_kernel(const float* __restrict__ adj,
                                                      float* __restrict__ hout,
                                                      float* __restrict__ adjout) {
    extern __shared__ __half sma[];
    const int bh = blockIdx.y;
    const int b = bh >> 4, h = bh & 15;
    const int qb = blockIdx.x;
    const int tid = threadIdx.x;
    const int warp = tid >> 5, lane = tid & 31, g = lane >> 2, tg = lane & 3;
    const int qrow = qb * 128 + warp * 16 + g;

    const int lt = lane >> 3, lrow = lane & 7;
    const int bRow = (lt >> 1) * 8 + lrow;
    const int bCol = (lt & 1) * 8;

    const int lr = tid >> 2;
    const int lcc = (tid & 3) * 16;

    // per stage: K | Vh | Vl, each [64][72] fp16
    auto load_tile = [&](int t) {
        __half* st = sma + (t % 3) * 3 * ASTG;
        size_t ko = ((size_t)bh * SQ + t * 64 + lr) * HD + lcc;
        size_t vo = ((size_t)bh * HD + lr) * SQ + t * 64 + lcc;
        __half* dst = st + lr * 72 + lcc;
        cp16(dst,            g_kh + ko);   cp16(dst + 8,            g_kh + ko + 8);
        cp16(dst + ASTG,     g_vth + vo);  cp16(dst + ASTG + 8,     g_vth + vo + 8);
        cp16(dst + 2 * ASTG, g_vtl + vo);  cp16(dst + 2 * ASTG + 8, g_vtl + vo + 8);
    };

    load_tile(0); CP_COMMIT();
    load_tile(1); CP_COMMIT();

    // fold adj pass-through copy (32 KB per CTA)
    {
        int flat = blockIdx.y * gridDim.x + blockIdx.x;
        const float4* asrc = (const float4*)adj;
        float4* adst = (float4*)adjout;
        size_t base = (size_t)flat * 2048;
        #pragma unroll
        for (int i = tid; i < 2048; i += 256)
            adst[base + i] = asrc[base + i];
    }

    // Q fragments (fp16, pre-scaled)
    uint32_t qA[4][4];
    {
        const __half* qh = g_qh + (size_t)bh * SQ * HD;
        #pragma unroll
        for (int kt = 0; kt < 4; kt++) {
            int c = kt * 16 + 2 * tg;
            qA[kt][0] = *(const uint32_t*)(qh + (size_t)qrow * HD + c);
            qA[kt][1] = *(const uint32_t*)(qh + (size_t)(qrow + 8) * HD + c);
            qA[kt][2] = *(const uint32_t*)(qh + (size_t)qrow * HD + c + 8);
            qA[kt][3] = *(const uint32_t*)(qh + (size_t)(qrow + 8) * HD + c + 8);
        }
    }

    float o[8][4];
    #pragma unroll
    for (int i = 0; i < 8; i++)
        #pragma unroll
        for (int j = 0; j < 4; j++) o[i][j] = 0.0f;
    float l0 = 0.0f, l1 = 0.0f;

    const float* adjr0 = adj + ((size_t)b * SQ + qrow) * SQ;
    const float* adjr1 = adjr0 + 8 * SQ;

    for (int t = 0; t < NTILE; t++) {
        if (t < NTILE - 1) { CP_WAIT1(); } else { CP_WAIT0(); }
        __syncthreads();
        if (t + 2 < NTILE) { load_tile(t + 2); CP_COMMIT(); }

        const __half* Kh = sma + (t % 3) * 3 * ASTG;
        const __half* Vh = Kh + ASTG;
        const __half* Vl = Kh + 2 * ASTG;
        const int kv0 = t * 64;

        // S2 = Q K^T (fp16 single-term; scale folded into Q)
        float s[8][4];
        #pragma unroll
        for (int i = 0; i < 8; i++)
            #pragma unroll
            for (int j = 0; j < 4; j++) s[i][j] = 0.0f;
        #pragma unroll
        for (int ntp = 0; ntp < 4; ntp++) {
            #pragma unroll
            for (int kt = 0; kt < 4; kt++) {
                uint32_t h0, h1, h2, h3;
                ldsm4(h0, h1, h2, h3, Kh + (ntp * 16 + bRow) * 72 + kt * 16 + bCol);
                mma_f16(s[2 * ntp],     qA[kt], h0, h1);
                mma_f16(s[2 * ntp + 1], qA[kt], h2, h3);
            }
        }

        // mask -> p = 2^s2, pack to fp16 A-fragments, accumulate l
        uint32_t pA[4][4];
        #pragma unroll
        for (int nt = 0; nt < 8; nt++) {
            int col = kv0 + nt * 8 + 2 * tg;
            float2 a0 = *(const float2*)(adjr0 + col);
            float2 a1 = *(const float2*)(adjr1 + col);
            float p0 = ex2(s[nt][0] + (a0.x < 0.5f ? NEG2 : 0.0f));
            float p1 = ex2(s[nt][1] + (a0.y < 0.5f ? NEG2 : 0.0f));
            float p2 = ex2(s[nt][2] + (a1.x < 0.5f ? NEG2 : 0.0f));
            float p3 = ex2(s[nt][3] + (a1.y < 0.5f ? NEG2 : 0.0f));
            l0 += p0 + p1;
            l1 += p2 + p3;
            int kt = nt >> 1;
            if ((nt & 1) == 0) {
                pA[kt][0] = packh2(p0, p1);
                pA[kt][1] = packh2(p2, p3);
            } else {
                pA[kt][2] = packh2(p0, p1);
                pA[kt][3] = packh2(p2, p3);
            }
        }

        // O += P V (p fp16, v hi+lo)
        #pragma unroll
        for (int ntp = 0; ntp < 4; ntp++) {
            #pragma unroll
            for (int kt = 0; kt < 4; kt++) {
                uint32_t vh0, vh1, vh2, vh3, vl0, vl1, vl2, vl3;
                ldsm4(vh0, vh1, vh2, vh3, Vh + (ntp * 16 + bRow) * 72 + kt * 16 + bCol);
                ldsm4(vl0, vl1, vl2, vl3, Vl + (ntp * 16 + bRow) * 72 + kt * 16 + bCol);
                mma_f16(o[2 * ntp],     pA[kt], vh0, vh1);
                mma_f16(o[2 * ntp],     pA[kt], vl0, vl1);
                mma_f16(o[2 * ntp + 1], pA[kt], vh2, vh3);
                mma_f16(o[2 * ntp + 1], pA[kt], vl2, vl3);
            }
        }
    }

    // deferred l-reduction across the quad
    l0 += __shfl_xor_sync(0xffffffff, l0, 1);
    l0 += __shfl_xor_sync(0xffffffff, l0, 2);
    l1 += __shfl_xor_sync(0xffffffff, l1, 1);
    l1 += __shfl_xor_sync(0xffffffff, l1, 2);

    float inv0 = 1.0f / l0, inv1 = 1.0f / l1;
    #pragma unroll
    for (int nt = 0; nt < 8; nt++) {
        int hd = nt * 8 + 2 * tg;
        float2 r0, r1;
        r0.x = fmaxf(o[nt][0] * inv0, 0.0f);
        r0.y = fmaxf(o[nt][1] * inv0, 0.0f);
        r1.x = fmaxf(o[nt][2] * inv1, 0.0f);
        r1.y = fmaxf(o[nt][3] * inv1, 0.0f);
        *(float2*)(hout + ((size_t)b * SQ + qrow) * DIM + h * HD + hd) = r0;
        *(float2*)(hout + ((size_t)b * SQ + qrow + 8) * DIM + h * HD + hd) = r1;
    }
}

// ---------------- launch ----------------
extern "C" void kernel_launch(void* const* d_in, const int* in_sizes, int n_in,
                              void* d_out, int out_size) {
    const float* x   = (const float*)d_in[0];
    const float* adj = (const float*)d_in[1];
    const float* Wq  = (const float*)d_in[2];
    const float* bq  = (const float*)d_in[3];
    const float* Wk  = (const float*)d_in[4];
    const float* bk  = (const float*)d_in[5];
    const float* Wv  = (const float*)d_in[6];
    const float* bv  = (const float*)d_in[7];

    float* hout   = (float*)d_out;
    float* adjout = (float*)d_out + (size_t)BN * SQ * DIM;

    const int qsmem = 2 * 3 * QSTG * (int)sizeof(__half);   // 61440
    const int asmem = 3 * 3 * ASTG * (int)sizeof(__half);   // 82944
    cudaFuncSetAttribute(qkv_gemm, cudaFuncAttributeMaxDynamicSharedMemorySize, qsmem);
    cudaFuncSetAttribute(attn_kernel, cudaFuncAttributeMaxDynamicSharedMemorySize, asmem);

    split_x_kernel<<<(BN * SQ * DIM) / (256 * 4), 256>>>(x);
    split_w_kernel<<<dim3(DIM / 32, DIM / 32, 3), dim3(32, 8)>>>(Wq, Wk, Wv);
    qkv_gemm<<<dim3(DIM / 128, (BN * SQ) / 128, 3), 256, qsmem>>>(bq, bk, bv);
    attn_kernel<<<dim3(SQ / 128, BH), 256, asmem>>>(adj, hout, adjout);
}

// round 15
// speedup vs baseline: 10.5967x; 1.4283x over previous
#include <cuda_runtime.h>
#include <cuda_fp16.h>
#include <cstdint>

#define BN 4
#define SQ 1024
#define DIM 1024
#define NH 16
#define HD 64
#define BH (BN*NH)
// exp2-domain: p = 2^(log2e*(q.k/8 + mask))
#define NEG2  (-10000000.0f * 1.44269504f)
#define QSCALE (0.125f * 1.44269504f)

// ---------------- scratch (device globals; no allocs allowed) ----------------
__device__ __half g_xh[BN*SQ*DIM];             // x fp16
__device__ __half g_wt[3*DIM*DIM];             // W^T fp16 [n][k]
__device__ __half g_qh[BH*SQ*HD];              // Q fp16, pre-scaled by 0.125*log2e
__device__ __half g_kh[BH*SQ*HD];              // K fp16
__device__ __half g_vth[BH*HD*SQ];             // V^T fp16  [bh][hd][s]

// ---------------- helpers ----------------
__device__ __forceinline__ uint32_t packh2(float a, float b) {
    __half2 h = __floats2half2_rn(a, b);
    return *reinterpret_cast<uint32_t*>(&h);
}

__device__ __forceinline__ float ex2(float x) {
    float y;
    asm("ex2.approx.ftz.f32 %0, %1;" : "=f"(y) : "f"(x));
    return y;
}

__device__ __forceinline__ void mma_f16(float* c, const uint32_t* a, uint32_t b0, uint32_t b1) {
    asm volatile(
        "mma.sync.aligned.m16n8k16.row.col.f32.f16.f16.f32 "
        "{%0,%1,%2,%3}, {%4,%5,%6,%7}, {%8,%9}, {%0,%1,%2,%3};\n"
        : "+f"(c[0]), "+f"(c[1]), "+f"(c[2]), "+f"(c[3])
        : "r"(a[0]), "r"(a[1]), "r"(a[2]), "r"(a[3]), "r"(b0), "r"(b1));
}

__device__ __forceinline__ void ldsm4(uint32_t& r0, uint32_t& r1, uint32_t& r2, uint32_t& r3,
                                      const void* p) {
    uint32_t a = (uint32_t)__cvta_generic_to_shared(p);
    asm volatile("ldmatrix.sync.aligned.m8n8.x4.shared.b16 {%0,%1,%2,%3}, [%4];\n"
                 : "=r"(r0), "=r"(r1), "=r"(r2), "=r"(r3) : "r"(a));
}

__device__ __forceinline__ void cp16(void* dst_smem, const void* src) {
    uint32_t d = (uint32_t)__cvta_generic_to_shared(dst_smem);
    asm volatile("cp.async.cg.shared.global [%0], [%1], 16;\n" :: "r"(d), "l"(src));
}
#define CP_COMMIT() asm volatile("cp.async.commit_group;\n")
#define CP_WAIT1()  asm volatile("cp.async.wait_group 1;\n")
#define CP_WAIT0()  asm volatile("cp.async.wait_group 0;\n")

// ---------------- 1) x -> fp16 ----------------
__global__ void split_x_kernel(const float* __restrict__ x) {
    size_t i = ((size_t)blockIdx.x * 256 + threadIdx.x) * 4;
    float4 v = *(const float4*)(x + i);
    uint2 hh;
    hh.x = packh2(v.x, v.y);
    hh.y = packh2(v.z, v.w);
    *(uint2*)(g_xh + i) = hh;
}

// ---------------- 2) transpose W -> Wt[n][k] fp16 ----------------
__global__ void split_w_kernel(const float* __restrict__ Wq,
                               const float* __restrict__ Wk,
                               const float* __restrict__ Wv) {
    __shared__ float t[32][33];
    int z = blockIdx.z;
    const float* W = (z == 0) ? Wq : (z == 1) ? Wk : Wv;
    __half* wt = g_wt + (size_t)z * DIM * DIM;
    int n0 = blockIdx.x * 32, k0 = blockIdx.y * 32;
    int tx = threadIdx.x, ty = threadIdx.y;
    #pragma unroll
    for (int r = 0; r < 4; r++)
        t[ty + 8 * r][tx] = W[(size_t)(k0 + ty + 8 * r) * DIM + n0 + tx];
    __syncthreads();
    #pragma unroll
    for (int r = 0; r < 4; r++) {
        float v = t[tx][ty + 8 * r];
        size_t idx = (size_t)(n0 + ty + 8 * r) * DIM + k0 + tx;
        wt[idx] = __float2half_rn(v);
    }
}

// ---------------- 3) QKV GEMM: fp16 single-term HMMA, 128x128 CTA tile ----------------
#define QSTG (128*40)
__global__ __launch_bounds__(256, 2) void qkv_gemm(const float* __restrict__ bq,
                                                   const float* __restrict__ bk,
                                                   const float* __restrict__ bv) {
    extern __shared__ __half smq[];
    const int z = blockIdx.z;
    const __half* wt = g_wt + (size_t)z * DIM * DIM;
    const float* bias = (z == 0) ? bq : (z == 1) ? bk : bv;
    const int m0 = blockIdx.y * 128, n0 = blockIdx.x * 128;
    const int tid = threadIdx.x;
    const int warp = tid >> 5, lane = tid & 31, g = lane >> 2, tg = lane & 3;
    const int wy = warp >> 2, wx = warp & 3;

    const int lt = lane >> 3, lrow = lane & 7;
    const int aRow = (lt & 1) * 8 + lrow;
    const int aCol = (lt >> 1) * 8;
    const int bRow = (lt >> 1) * 8 + lrow;
    const int bCol = (lt & 1) * 8;

    const int lr = tid >> 1;
    const int lcc = (tid & 1) * 16;

    float acc[4][4][4];
    #pragma unroll
    for (int a = 0; a < 4; a++)
        #pragma unroll
        for (int b = 0; b < 4; b++)
            #pragma unroll
            for (int c = 0; c < 4; c++) acc[a][b][c] = 0.0f;

    {
        __half* st = smq;
        size_t xo = (size_t)(m0 + lr) * DIM + lcc;
        size_t wo = (size_t)(n0 + lr) * DIM + lcc;
        __half* dst = st + lr * 40 + lcc;
        cp16(dst,        g_xh + xo);  cp16(dst + 8,        g_xh + xo + 8);
        cp16(dst + QSTG, wt + wo);    cp16(dst + QSTG + 8, wt + wo + 8);
        CP_COMMIT();
    }

    for (int it = 0; it < DIM / 32; it++) {
        const int cur = it & 1;
        const int k0 = it * 32;
        if (k0 + 32 < DIM) {
            __half* st = smq + (cur ^ 1) * 2 * QSTG;
            size_t xo = (size_t)(m0 + lr) * DIM + k0 + 32 + lcc;
            size_t wo = (size_t)(n0 + lr) * DIM + k0 + 32 + lcc;
            __half* dst = st + lr * 40 + lcc;
            cp16(dst,        g_xh + xo);  cp16(dst + 8,        g_xh + xo + 8);
            cp16(dst + QSTG, wt + wo);    cp16(dst + QSTG + 8, wt + wo + 8);
            CP_COMMIT();
            CP_WAIT1();
        } else {
            CP_WAIT0();
        }
        __syncthreads();

        const __half* Xh = smq + cur * 2 * QSTG;
        const __half* Wh = Xh + QSTG;

        #pragma unroll
        for (int kt = 0; kt < 2; kt++) {
            const int cI = kt * 16;
            uint32_t ah[4][4];
            #pragma unroll
            for (int mt = 0; mt < 4; mt++) {
                int r = wy * 64 + mt * 16 + aRow;
                ldsm4(ah[mt][0], ah[mt][1], ah[mt][2], ah[mt][3], Xh + r * 40 + cI + aCol);
            }
            #pragma unroll
            for (int ntp = 0; ntp < 2; ntp++) {
                int rn = wx * 32 + ntp * 16 + bRow;
                uint32_t h0, h1, h2, h3;
                ldsm4(h0, h1, h2, h3, Wh + rn * 40 + cI + bCol);
                #pragma unroll
                for (int mt = 0; mt < 4; mt++) {
                    mma_f16(acc[mt][2 * ntp],     ah[mt], h0, h1);
                    mma_f16(acc[mt][2 * ntp + 1], ah[mt], h2, h3);
                }
            }
        }
        __syncthreads();
    }

    // epilogue: +bias; Q scaled into exp2 domain; all outputs single fp16
    #pragma unroll
    for (int mt = 0; mt < 4; mt++) {
        #pragma unroll
        for (int nt = 0; nt < 4; nt++) {
            int n = n0 + wx * 32 + nt * 8 + 2 * tg;
            float b0 = bias[n], b1 = bias[n + 1];
            int hh = n >> 6, hd = n & 63;
            #pragma unroll
            for (int half = 0; half < 2; half++) {
                int m = m0 + wy * 64 + mt * 16 + g + half * 8;
                float v0 = acc[mt][nt][half * 2 + 0] + b0;
                float v1 = acc[mt][nt][half * 2 + 1] + b1;
                int bb = m >> 10, s = m & 1023;
                if (z == 0) {
                    size_t base = ((size_t)(bb * NH + hh) * SQ + s) * HD + hd;
                    *(uint32_t*)(g_qh + base) = packh2(v0 * QSCALE, v1 * QSCALE);
                } else if (z == 1) {
                    size_t base = ((size_t)(bb * NH + hh) * SQ + s) * HD + hd;
                    *(uint32_t*)(g_kh + base) = packh2(v0, v1);
                } else {
                    size_t v0i = ((size_t)(bb * NH + hh) * HD + hd) * SQ + s;
                    g_vth[v0i]      = __float2half_rn(v0);
                    g_vth[v0i + SQ] = __float2half_rn(v1);
                }
            }
        }
    }
}

// ---------------- 4) attention: fp16 single-term, no-rescale softmax ----------------
#define ASTG (64*72)
#define NTILE (SQ/64)
__global__ __launch_bounds__(256, 2) void attn_kernel(const float* __restrict__ adj,
                                                      float* __restrict__ hout,
                                                      float* __restrict__ adjout) {
    extern __shared__ __half sma[];
    const int bh = blockIdx.y;
    const int b = bh >> 4, h = bh & 15;
    const int qb = blockIdx.x;
    const int tid = threadIdx.x;
    const int warp = tid >> 5, lane = tid & 31, g = lane >> 2, tg = lane & 3;
    const int qrow = qb * 128 + warp * 16 + g;

    const int lt = lane >> 3, lrow = lane & 7;
    const int bRow = (lt >> 1) * 8 + lrow;
    const int bCol = (lt & 1) * 8;

    const int lr = tid >> 2;
    const int lcc = (tid & 3) * 16;

    // per stage: K | V, each [64][72] fp16
    auto load_tile = [&](int t) {
        __half* st = sma + (t % 3) * 2 * ASTG;
        size_t ko = ((size_t)bh * SQ + t * 64 + lr) * HD + lcc;
        size_t vo = ((size_t)bh * HD + lr) * SQ + t * 64 + lcc;
        __half* dst = st + lr * 72 + lcc;
        cp16(dst,        g_kh + ko);   cp16(dst + 8,        g_kh + ko + 8);
        cp16(dst + ASTG, g_vth + vo);  cp16(dst + ASTG + 8, g_vth + vo + 8);
    };

    load_tile(0); CP_COMMIT();
    load_tile(1); CP_COMMIT();

    // fold adj pass-through copy (32 KB per CTA)
    {
        int flat = blockIdx.y * gridDim.x + blockIdx.x;
        const float4* asrc = (const float4*)adj;
        float4* adst = (float4*)adjout;
        size_t base = (size_t)flat * 2048;
        #pragma unroll
        for (int i = tid; i < 2048; i += 256)
            adst[base + i] = asrc[base + i];
    }

    // Q fragments (fp16, pre-scaled)
    uint32_t qA[4][4];
    {
        const __half* qh = g_qh + (size_t)bh * SQ * HD;
        #pragma unroll
        for (int kt = 0; kt < 4; kt++) {
            int c = kt * 16 + 2 * tg;
            qA[kt][0] = *(const uint32_t*)(qh + (size_t)qrow * HD + c);
            qA[kt][1] = *(const uint32_t*)(qh + (size_t)(qrow + 8) * HD + c);
            qA[kt][2] = *(const uint32_t*)(qh + (size_t)qrow * HD + c + 8);
            qA[kt][3] = *(const uint32_t*)(qh + (size_t)(qrow + 8) * HD + c + 8);
        }
    }

    float o[8][4];
    #pragma unroll
    for (int i = 0; i < 8; i++)
        #pragma unroll
        for (int j = 0; j < 4; j++) o[i][j] = 0.0f;
    float l0 = 0.0f, l1 = 0.0f;

    const float* adjr0 = adj + ((size_t)b * SQ + qrow) * SQ;
    const float* adjr1 = adjr0 + 8 * SQ;

    for (int t = 0; t < NTILE; t++) {
        if (t < NTILE - 1) { CP_WAIT1(); } else { CP_WAIT0(); }
        __syncthreads();
        if (t + 2 < NTILE) { load_tile(t + 2); CP_COMMIT(); }

        const __half* Kh = sma + (t % 3) * 2 * ASTG;
        const __half* Vh = Kh + ASTG;
        const int kv0 = t * 64;

        // S2 = Q K^T (fp16; scale folded into Q)
        float s[8][4];
        #pragma unroll
        for (int i = 0; i < 8; i++)
            #pragma unroll
            for (int j = 0; j < 4; j++) s[i][j] = 0.0f;
        #pragma unroll
        for (int ntp = 0; ntp < 4; ntp++) {
            #pragma unroll
            for (int kt = 0; kt < 4; kt++) {
                uint32_t h0, h1, h2, h3;
                ldsm4(h0, h1, h2, h3, Kh + (ntp * 16 + bRow) * 72 + kt * 16 + bCol);
                mma_f16(s[2 * ntp],     qA[kt], h0, h1);
                mma_f16(s[2 * ntp + 1], qA[kt], h2, h3);
            }
        }

        // mask -> p = 2^s2, pack to fp16 A-fragments, accumulate l
        uint32_t pA[4][4];
        #pragma unroll
        for (int nt = 0; nt < 8; nt++) {
            int col = kv0 + nt * 8 + 2 * tg;
            float2 a0 = *(const float2*)(adjr0 + col);
            float2 a1 = *(const float2*)(adjr1 + col);
            float p0 = ex2(s[nt][0] + (a0.x < 0.5f ? NEG2 : 0.0f));
            float p1 = ex2(s[nt][1] + (a0.y < 0.5f ? NEG2 : 0.0f));
            float p2 = ex2(s[nt][2] + (a1.x < 0.5f ? NEG2 : 0.0f));
            float p3 = ex2(s[nt][3] + (a1.y < 0.5f ? NEG2 : 0.0f));
            l0 += p0 + p1;
            l1 += p2 + p3;
            int kt = nt >> 1;
            if ((nt & 1) == 0) {
                pA[kt][0] = packh2(p0, p1);
                pA[kt][1] = packh2(p2, p3);
            } else {
                pA[kt][2] = packh2(p0, p1);
                pA[kt][3] = packh2(p2, p3);
            }
        }

        // O += P V (single fp16 term)
        #pragma unroll
        for (int ntp = 0; ntp < 4; ntp++) {
            #pragma unroll
            for (int kt = 0; kt < 4; kt++) {
                uint32_t vh0, vh1, vh2, vh3;
                ldsm4(vh0, vh1, vh2, vh3, Vh + (ntp * 16 + bRow) * 72 + kt * 16 + bCol);
                mma_f16(o[2 * ntp],     pA[kt], vh0, vh1);
                mma_f16(o[2 * ntp + 1], pA[kt], vh2, vh3);
            }
        }
    }

    // deferred l-reduction across the quad
    l0 += __shfl_xor_sync(0xffffffff, l0, 1);
    l0 += __shfl_xor_sync(0xffffffff, l0, 2);
    l1 += __shfl_xor_sync(0xffffffff, l1, 1);
    l1 += __shfl_xor_sync(0xffffffff, l1, 2);

    float inv0 = 1.0f / l0, inv1 = 1.0f / l1;
    #pragma unroll
    for (int nt = 0; nt < 8; nt++) {
        int hd = nt * 8 + 2 * tg;
        float2 r0, r1;
        r0.x = fmaxf(o[nt][0] * inv0, 0.0f);
        r0.y = fmaxf(o[nt][1] * inv0, 0.0f);
        r1.x = fmaxf(o[nt][2] * inv1, 0.0f);
        r1.y = fmaxf(o[nt][3] * inv1, 0.0f);
        *(float2*)(hout + ((size_t)b * SQ + qrow) * DIM + h * HD + hd) = r0;
        *(float2*)(hout + ((size_t)b * SQ + qrow + 8) * DIM + h * HD + hd) = r1;
    }
}

// ---------------- launch ----------------
extern "C" void kernel_launch(void* const* d_in, const int* in_sizes, int n_in,
                              void* d_out, int out_size) {
    const float* x   = (const float*)d_in[0];
    const float* adj = (const float*)d_in[1];
    const float* Wq  = (const float*)d_in[2];
    const float* bq  = (const float*)d_in[3];
    const float* Wk  = (const float*)d_in[4];
    const float* bk  = (const float*)d_in[5];
    const float* Wv  = (const float*)d_in[6];
    const float* bv  = (const float*)d_in[7];

    float* hout   = (float*)d_out;
    float* adjout = (float*)d_out + (size_t)BN * SQ * DIM;

    const int qsmem = 2 * 2 * QSTG * (int)sizeof(__half);   // 40960
    const int asmem = 3 * 2 * ASTG * (int)sizeof(__half);   // 55296
    cudaFuncSetAttribute(qkv_gemm, cudaFuncAttributeMaxDynamicSharedMemorySize, qsmem);
    cudaFuncSetAttribute(attn_kernel, cudaFuncAttributeMaxDynamicSharedMemorySize, asmem);

    split_x_kernel<<<(BN * SQ * DIM) / (256 * 4), 256>>>(x);
    split_w_kernel<<<dim3(DIM / 32, DIM / 32, 3), dim3(32, 8)>>>(Wq, Wk, Wv);
    qkv_gemm<<<dim3(DIM / 128, (BN * SQ) / 128, 3), 256, qsmem>>>(bq, bk, bv);
    attn_kernel<<<dim3(SQ / 128, BH), 256, asmem>>>(adj, hout, adjout);
}

// round 16
// speedup vs baseline: 10.7572x; 1.0151x over previous
#include <cuda_runtime.h>
#include <cuda_fp16.h>
#include <cstdint>

#define BN 4
#define SQ 1024
#define DIM 1024
#define NH 16
#define HD 64
#define BH (BN*NH)
// exp2-domain: p = 2^(log2e*(q.k/8 + mask))
#define NEG2  (-10000000.0f * 1.44269504f)
#define QSCALE (0.125f * 1.44269504f)

// ---------------- scratch (device globals; no allocs allowed) ----------------
__device__ __half g_xh[BN*SQ*DIM];             // x fp16
__device__ __half g_wt[3*DIM*DIM];             // W^T fp16 [n][k]
__device__ __half g_qh[BH*SQ*HD];              // Q fp16, pre-scaled by 0.125*log2e
__device__ __half g_kh[BH*SQ*HD];              // K fp16
__device__ __half g_vth[BH*HD*SQ];             // V^T fp16  [bh][hd][s]

// ---------------- helpers ----------------
__device__ __forceinline__ uint32_t packh2(float a, float b) {
    __half2 h = __floats2half2_rn(a, b);
    return *reinterpret_cast<uint32_t*>(&h);
}

__device__ __forceinline__ float ex2(float x) {
    float y;
    asm("ex2.approx.ftz.f32 %0, %1;" : "=f"(y) : "f"(x));
    return y;
}

__device__ __forceinline__ void mma_f16(float* c, const uint32_t* a, uint32_t b0, uint32_t b1) {
    asm volatile(
        "mma.sync.aligned.m16n8k16.row.col.f32.f16.f16.f32 "
        "{%0,%1,%2,%3}, {%4,%5,%6,%7}, {%8,%9}, {%0,%1,%2,%3};\n"
        : "+f"(c[0]), "+f"(c[1]), "+f"(c[2]), "+f"(c[3])
        : "r"(a[0]), "r"(a[1]), "r"(a[2]), "r"(a[3]), "r"(b0), "r"(b1));
}

__device__ __forceinline__ void ldsm4(uint32_t& r0, uint32_t& r1, uint32_t& r2, uint32_t& r3,
                                      const void* p) {
    uint32_t a = (uint32_t)__cvta_generic_to_shared(p);
    asm volatile("ldmatrix.sync.aligned.m8n8.x4.shared.b16 {%0,%1,%2,%3}, [%4];\n"
                 : "=r"(r0), "=r"(r1), "=r"(r2), "=r"(r3) : "r"(a));
}

__device__ __forceinline__ void cp16(void* dst_smem, const void* src) {
    uint32_t d = (uint32_t)__cvta_generic_to_shared(dst_smem);
    asm volatile("cp.async.cg.shared.global [%0], [%1], 16;\n" :: "r"(d), "l"(src));
}
#define CP_COMMIT() asm volatile("cp.async.commit_group;\n")
#define CP_WAIT1()  asm volatile("cp.async.wait_group 1;\n")
#define CP_WAIT0()  asm volatile("cp.async.wait_group 0;\n")

// ---------------- 1) x -> fp16 ----------------
__global__ void split_x_kernel(const float* __restrict__ x) {
    size_t i = ((size_t)blockIdx.x * 256 + threadIdx.x) * 4;
    float4 v = *(const float4*)(x + i);
    uint2 hh;
    hh.x = packh2(v.x, v.y);
    hh.y = packh2(v.z, v.w);
    *(uint2*)(g_xh + i) = hh;
}

// ---------------- 2) transpose W -> Wt[n][k] fp16 ----------------
__global__ void split_w_kernel(const float* __restrict__ Wq,
                               const float* __restrict__ Wk,
                               const float* __restrict__ Wv) {
    __shared__ float t[32][33];
    int z = blockIdx.z;
    const float* W = (z == 0) ? Wq : (z == 1) ? Wk : Wv;
    __half* wt = g_wt + (size_t)z * DIM * DIM;
    int n0 = blockIdx.x * 32, k0 = blockIdx.y * 32;
    int tx = threadIdx.x, ty = threadIdx.y;
    #pragma unroll
    for (int r = 0; r < 4; r++)
        t[ty + 8 * r][tx] = W[(size_t)(k0 + ty + 8 * r) * DIM + n0 + tx];
    __syncthreads();
    #pragma unroll
    for (int r = 0; r < 4; r++) {
        float v = t[tx][ty + 8 * r];
        size_t idx = (size_t)(n0 + ty + 8 * r) * DIM + k0 + tx;
        wt[idx] = __float2half_rn(v);
    }
}

// ---------------- 3) QKV GEMM: fp16 single-term HMMA, 128x128 CTA tile ----------------
#define QSTG (128*40)
__global__ __launch_bounds__(256, 2) void qkv_gemm(const float* __restrict__ bq,
                                                   const float* __restrict__ bk,
                                                   const float* __restrict__ bv) {
    extern __shared__ __half smq[];
    const int z = blockIdx.z;
    const __half* wt = g_wt + (size_t)z * DIM * DIM;
    const float* bias = (z == 0) ? bq : (z == 1) ? bk : bv;
    const int m0 = blockIdx.y * 128, n0 = blockIdx.x * 128;
    const int tid = threadIdx.x;
    const int warp = tid >> 5, lane = tid & 31, g = lane >> 2, tg = lane & 3;
    const int wy = warp >> 2, wx = warp & 3;

    const int lt = lane >> 3, lrow = lane & 7;
    const int aRow = (lt & 1) * 8 + lrow;
    const int aCol = (lt >> 1) * 8;
    const int bRow = (lt >> 1) * 8 + lrow;
    const int bCol = (lt & 1) * 8;

    const int lr = tid >> 1;
    const int lcc = (tid & 1) * 16;

    float acc[4][4][4];
    #pragma unroll
    for (int a = 0; a < 4; a++)
        #pragma unroll
        for (int b = 0; b < 4; b++)
            #pragma unroll
            for (int c = 0; c < 4; c++) acc[a][b][c] = 0.0f;

    {
        __half* st = smq;
        size_t xo = (size_t)(m0 + lr) * DIM + lcc;
        size_t wo = (size_t)(n0 + lr) * DIM + lcc;
        __half* dst = st + lr * 40 + lcc;
        cp16(dst,        g_xh + xo);  cp16(dst + 8,        g_xh + xo + 8);
        cp16(dst + QSTG, wt + wo);    cp16(dst + QSTG + 8, wt + wo + 8);
        CP_COMMIT();
    }

    for (int it = 0; it < DIM / 32; it++) {
        const int cur = it & 1;
        const int k0 = it * 32;
        if (k0 + 32 < DIM) {
            __half* st = smq + (cur ^ 1) * 2 * QSTG;
            size_t xo = (size_t)(m0 + lr) * DIM + k0 + 32 + lcc;
            size_t wo = (size_t)(n0 + lr) * DIM + k0 + 32 + lcc;
            __half* dst = st + lr * 40 + lcc;
            cp16(dst,        g_xh + xo);  cp16(dst + 8,        g_xh + xo + 8);
            cp16(dst + QSTG, wt + wo);    cp16(dst + QSTG + 8, wt + wo + 8);
            CP_COMMIT();
            CP_WAIT1();
        } else {
            CP_WAIT0();
        }
        __syncthreads();

        const __half* Xh = smq + cur * 2 * QSTG;
        const __half* Wh = Xh + QSTG;

        #pragma unroll
        for (int kt = 0; kt < 2; kt++) {
            const int cI = kt * 16;
            uint32_t ah[4][4];
            #pragma unroll
            for (int mt = 0; mt < 4; mt++) {
                int r = wy * 64 + mt * 16 + aRow;
                ldsm4(ah[mt][0], ah[mt][1], ah[mt][2], ah[mt][3], Xh + r * 40 + cI + aCol);
            }
            #pragma unroll
            for (int ntp = 0; ntp < 2; ntp++) {
                int rn = wx * 32 + ntp * 16 + bRow;
                uint32_t h0, h1, h2, h3;
                ldsm4(h0, h1, h2, h3, Wh + rn * 40 + cI + bCol);
                #pragma unroll
                for (int mt = 0; mt < 4; mt++) {
                    mma_f16(acc[mt][2 * ntp],     ah[mt], h0, h1);
                    mma_f16(acc[mt][2 * ntp + 1], ah[mt], h2, h3);
                }
            }
        }
        __syncthreads();
    }

    // epilogue: +bias; Q scaled into exp2 domain; all outputs single fp16
    #pragma unroll
    for (int mt = 0; mt < 4; mt++) {
        #pragma unroll
        for (int nt = 0; nt < 4; nt++) {
            int n = n0 + wx * 32 + nt * 8 + 2 * tg;
            float b0 = bias[n], b1 = bias[n + 1];
            int hh = n >> 6, hd = n & 63;
            #pragma unroll
            for (int half = 0; half < 2; half++) {
                int m = m0 + wy * 64 + mt * 16 + g + half * 8;
                float v0 = acc[mt][nt][half * 2 + 0] + b0;
                float v1 = acc[mt][nt][half * 2 + 1] + b1;
                int bb = m >> 10, s = m & 1023;
                if (z == 0) {
                    size_t base = ((size_t)(bb * NH + hh) * SQ + s) * HD + hd;
                    *(uint32_t*)(g_qh + base) = packh2(v0 * QSCALE, v1 * QSCALE);
                } else if (z == 1) {
                    size_t base = ((size_t)(bb * NH + hh) * SQ + s) * HD + hd;
                    *(uint32_t*)(g_kh + base) = packh2(v0, v1);
                } else {
                    size_t v0i = ((size_t)(bb * NH + hh) * HD + hd) * SQ + s;
                    g_vth[v0i]      = __float2half_rn(v0);
                    g_vth[v0i + SQ] = __float2half_rn(v1);
                }
            }
        }
    }
}

// ---------------- 4) attention: fp16, cross-tile software pipeline ----------------
// iter t issues QK(t) MMAs + PV(t-1) MMAs back-to-back, then softmax(t) -> pA.
// 4-stage smem ring keeps V(t-1) alive one extra iteration.
#define ASTG (64*72)
#define NTILE (SQ/64)
__global__ __launch_bounds__(256, 2) void attn_kernel(const float* __restrict__ adj,
                                                      float* __restrict__ hout,
                                                      float* __restrict__ adjout) {
    extern __shared__ __half sma[];
    const int bh = blockIdx.y;
    const int b = bh >> 4, h = bh & 15;
    const int qb = blockIdx.x;
    const int tid = threadIdx.x;
    const int warp = tid >> 5, lane = tid & 31, g = lane >> 2, tg = lane & 3;
    const int qrow = qb * 128 + warp * 16 + g;

    const int lt = lane >> 3, lrow = lane & 7;
    const int bRow = (lt >> 1) * 8 + lrow;
    const int bCol = (lt & 1) * 8;

    const int lr = tid >> 2;
    const int lcc = (tid & 3) * 16;

    // per stage: K | V, each [64][72] fp16; 4-stage ring
    auto load_tile = [&](int t) {
        __half* st = sma + (t & 3) * 2 * ASTG;
        size_t ko = ((size_t)bh * SQ + t * 64 + lr) * HD + lcc;
        size_t vo = ((size_t)bh * HD + lr) * SQ + t * 64 + lcc;
        __half* dst = st + lr * 72 + lcc;
        cp16(dst,        g_kh + ko);   cp16(dst + 8,        g_kh + ko + 8);
        cp16(dst + ASTG, g_vth + vo);  cp16(dst + ASTG + 8, g_vth + vo + 8);
    };

    load_tile(0); CP_COMMIT();
    load_tile(1); CP_COMMIT();

    // fold adj pass-through copy (32 KB per CTA)
    {
        int flat = blockIdx.y * gridDim.x + blockIdx.x;
        const float4* asrc = (const float4*)adj;
        float4* adst = (float4*)adjout;
        size_t base = (size_t)flat * 2048;
        #pragma unroll
        for (int i = tid; i < 2048; i += 256)
            adst[base + i] = asrc[base + i];
    }

    // Q fragments (fp16, pre-scaled)
    uint32_t qA[4][4];
    {
        const __half* qh = g_qh + (size_t)bh * SQ * HD;
        #pragma unroll
        for (int kt = 0; kt < 4; kt++) {
            int c = kt * 16 + 2 * tg;
            qA[kt][0] = *(const uint32_t*)(qh + (size_t)qrow * HD + c);
            qA[kt][1] = *(const uint32_t*)(qh + (size_t)(qrow + 8) * HD + c);
            qA[kt][2] = *(const uint32_t*)(qh + (size_t)qrow * HD + c + 8);
            qA[kt][3] = *(const uint32_t*)(qh + (size_t)(qrow + 8) * HD + c + 8);
        }
    }

    float o[8][4];
    #pragma unroll
    for (int i = 0; i < 8; i++)
        #pragma unroll
        for (int j = 0; j < 4; j++) o[i][j] = 0.0f;
    float l0 = 0.0f, l1 = 0.0f;
    uint32_t pA[4][4];   // probs of tile t-1, consumed at iter t

    const float* adjr0 = adj + ((size_t)b * SQ + qrow) * SQ;
    const float* adjr1 = adjr0 + 8 * SQ;

    for (int t = 0; t < NTILE; t++) {
        if (t < NTILE - 1) { CP_WAIT1(); } else { CP_WAIT0(); }
        __syncthreads();
        if (t + 2 < NTILE) { load_tile(t + 2); CP_COMMIT(); }

        const __half* Kh = sma + (t & 3) * 2 * ASTG;
        const int kv0 = t * 64;

        // QK(t): S2 = Q K^T (fp16; scale folded into Q)
        float s[8][4];
        #pragma unroll
        for (int i = 0; i < 8; i++)
            #pragma unroll
            for (int j = 0; j < 4; j++) s[i][j] = 0.0f;
        #pragma unroll
        for (int ntp = 0; ntp < 4; ntp++) {
            #pragma unroll
            for (int kt = 0; kt < 4; kt++) {
                uint32_t h0, h1, h2, h3;
                ldsm4(h0, h1, h2, h3, Kh + (ntp * 16 + bRow) * 72 + kt * 16 + bCol);
                mma_f16(s[2 * ntp],     qA[kt], h0, h1);
                mma_f16(s[2 * ntp + 1], qA[kt], h2, h3);
            }
        }

        // PV(t-1): overlapped with (hides) the QK->softmax dependency
        if (t > 0) {
            const __half* Vp = sma + ((t - 1) & 3) * 2 * ASTG + ASTG;
            #pragma unroll
            for (int ntp = 0; ntp < 4; ntp++) {
                #pragma unroll
                for (int kt = 0; kt < 4; kt++) {
                    uint32_t vh0, vh1, vh2, vh3;
                    ldsm4(vh0, vh1, vh2, vh3, Vp + (ntp * 16 + bRow) * 72 + kt * 16 + bCol);
                    mma_f16(o[2 * ntp],     pA[kt], vh0, vh1);
                    mma_f16(o[2 * ntp + 1], pA[kt], vh2, vh3);
                }
            }
        }

        // softmax(t): mask -> p = 2^s2, pack to fp16 A-fragments, accumulate l
        #pragma unroll
        for (int nt = 0; nt < 8; nt++) {
            int col = kv0 + nt * 8 + 2 * tg;
            float2 a0 = *(const float2*)(adjr0 + col);
            float2 a1 = *(const float2*)(adjr1 + col);
            float p0 = ex2(s[nt][0] + (a0.x < 0.5f ? NEG2 : 0.0f));
            float p1 = ex2(s[nt][1] + (a0.y < 0.5f ? NEG2 : 0.0f));
            float p2 = ex2(s[nt][2] + (a1.x < 0.5f ? NEG2 : 0.0f));
            float p3 = ex2(s[nt][3] + (a1.y < 0.5f ? NEG2 : 0.0f));
            l0 += p0 + p1;
            l1 += p2 + p3;
            int kt = nt >> 1;
            if ((nt & 1) == 0) {
                pA[kt][0] = packh2(p0, p1);
                pA[kt][1] = packh2(p2, p3);
            } else {
                pA[kt][2] = packh2(p0, p1);
                pA[kt][3] = packh2(p2, p3);
            }
        }
    }

    // tail: PV(NTILE-1)
    {
        const __half* Vp = sma + ((NTILE - 1) & 3) * 2 * ASTG + ASTG;
        #pragma unroll
        for (int ntp = 0; ntp < 4; ntp++) {
            #pragma unroll
            for (int kt = 0; kt < 4; kt++) {
                uint32_t vh0, vh1, vh2, vh3;
                ldsm4(vh0, vh1, vh2, vh3, Vp + (ntp * 16 + bRow) * 72 + kt * 16 + bCol);
                mma_f16(o[2 * ntp],     pA[kt], vh0, vh1);
                mma_f16(o[2 * ntp + 1], pA[kt], vh2, vh3);
            }
        }
    }

    // deferred l-reduction across the quad
    l0 += __shfl_xor_sync(0xffffffff, l0, 1);
    l0 += __shfl_xor_sync(0xffffffff, l0, 2);
    l1 += __shfl_xor_sync(0xffffffff, l1, 1);
    l1 += __shfl_xor_sync(0xffffffff, l1, 2);

    float inv0 = 1.0f / l0, inv1 = 1.0f / l1;
    #pragma unroll
    for (int nt = 0; nt < 8; nt++) {
        int hd = nt * 8 + 2 * tg;
        float2 r0, r1;
        r0.x = fmaxf(o[nt][0] * inv0, 0.0f);
        r0.y = fmaxf(o[nt][1] * inv0, 0.0f);
        r1.x = fmaxf(o[nt][2] * inv1, 0.0f);
        r1.y = fmaxf(o[nt][3] * inv1, 0.0f);
        *(float2*)(hout + ((size_t)b * SQ + qrow) * DIM + h * HD + hd) = r0;
        *(float2*)(hout + ((size_t)b * SQ + qrow + 8) * DIM + h * HD + hd) = r1;
    }
}

// ---------------- launch ----------------
extern "C" void kernel_launch(void* const* d_in, const int* in_sizes, int n_in,
                              void* d_out, int out_size) {
    const float* x   = (const float*)d_in[0];
    const float* adj = (const float*)d_in[1];
    const float* Wq  = (const float*)d_in[2];
    const float* bq  = (const float*)d_in[3];
    const float* Wk  = (const float*)d_in[4];
    const float* bk  = (const float*)d_in[5];
    const float* Wv  = (const float*)d_in[6];
    const float* bv  = (const float*)d_in[7];

    float* hout   = (float*)d_out;
    float* adjout = (float*)d_out + (size_t)BN * SQ * DIM;

    const int qsmem = 2 * 2 * QSTG * (int)sizeof(__half);   // 40960
    const int asmem = 4 * 2 * ASTG * (int)sizeof(__half);   // 73728
    cudaFuncSetAttribute(qkv_gemm, cudaFuncAttributeMaxDynamicSharedMemorySize, qsmem);
    cudaFuncSetAttribute(attn_kernel, cudaFuncAttributeMaxDynamicSharedMemorySize, asmem);

    split_x_kernel<<<(BN * SQ * DIM) / (256 * 4), 256>>>(x);
    split_w_kernel<<<dim3(DIM / 32, DIM / 32, 3), dim3(32, 8)>>>(Wq, Wk, Wv);
    qkv_gemm<<<dim3(DIM / 128, (BN * SQ) / 128, 3), 256, qsmem>>>(bq, bk, bv);
    attn_kernel<<<dim3(SQ / 128, BH), 256, asmem>>>(adj, hout, adjout);
}